// round 15
// baseline (speedup 1.0000x reference)
#include <cuda_runtime.h>
#include <cuda.h>
#include <cuda_bf16.h>
#include <math_constants.h>
#include <cstdint>

#define BATCH 16
#define DEC   2048
#define ENC   2048
#define HDIM  1024

#if defined(__CUDA_ARCH_SPECIFIC__) || defined(__CUDA_ARCH_FEAT_SM103_ALL) || defined(__CUDA_ARCH_FEAT_SM100_ALL)
#define TC_OK 1
#else
#define TC_OK 0
#endif

typedef __nv_bfloat16 bf16;

// ---------------------------------------------------------------------------
// Scratch (static device globals)
// ---------------------------------------------------------------------------
__device__ bf16 g_Dhi [(size_t)BATCH * DEC  * HDIM];
__device__ bf16 g_Dlo [(size_t)BATCH * DEC  * HDIM];
__device__ bf16 g_Ehi [(size_t)BATCH * ENC  * HDIM];
__device__ bf16 g_Elo [(size_t)BATCH * ENC  * HDIM];
__device__ bf16 g_EThi[(size_t)BATCH * HDIM * ENC ];
__device__ bf16 g_ETlo[(size_t)BATCH * HDIM * ENC ];
__device__ bf16 g_Phi [(size_t)BATCH * DEC  * ENC ];
__device__ bf16 g_Plo [(size_t)BATCH * DEC  * ENC ];

// ---------------------------------------------------------------------------
// PTX helpers
// ---------------------------------------------------------------------------
__device__ __forceinline__ uint32_t smem_u32(const void* p) {
    uint32_t a;
    asm("{ .reg .u64 t; cvta.to.shared.u64 t, %1; cvt.u32.u64 %0, t; }"
        : "=r"(a) : "l"(p));
    return a;
}

__device__ __forceinline__ bool elect_one() {
    uint32_t p;
    asm volatile("{\n .reg .pred p;\n elect.sync _|p, 0xFFFFFFFF;\n"
                 " selp.b32 %0, 1, 0, p;\n}" : "=r"(p));
    return p != 0;
}

#define SWZ128(b) ((b) ^ (((b) >> 3) & 0x70))

__device__ __forceinline__ void cpasync16(uint32_t s, const void* g) {
    asm volatile("cp.async.cg.shared.global [%0], [%1], 16;"
                 :: "r"(s), "l"(g) : "memory");
}

__device__ __forceinline__ void mbar_init(uint32_t m, uint32_t cnt) {
    asm volatile("mbarrier.init.shared.b64 [%0], %1;" :: "r"(m), "r"(cnt) : "memory");
}

__device__ __forceinline__ void mbar_expect(uint32_t m, uint32_t tx) {
    asm volatile("mbarrier.arrive.expect_tx.shared.b64 _, [%0], %1;"
                 :: "r"(m), "r"(tx) : "memory");
}

__device__ __forceinline__ void mbar_wait(uint32_t m, uint32_t phase) {
    asm volatile(
        "{\n .reg .pred P;\n"
        "LAB%=:\n"
        " mbarrier.try_wait.parity.acquire.cta.shared::cta.b64 P, [%0], %1, 0x989680;\n"
        " @P bra DONE%=;\n"
        " bra LAB%=;\n"
        "DONE%=:\n}"
        :: "r"(m), "r"(phase) : "memory");
}

#define CLUSTER_SYNC_ALL() do { \
    asm volatile("barrier.cluster.arrive.aligned;" ::: "memory"); \
    asm volatile("barrier.cluster.wait.aligned;"   ::: "memory"); \
} while (0)

// K-major SMEM descriptors (Blackwell, version=1)
static constexpr uint64_t DESC_BASE_SW128 =
    (2ull << 61) | (1ull << 46) | (64ull << 32) | (1ull << 16);
static constexpr uint64_t DESC_BASE_SW64 =
    (4ull << 61) | (1ull << 46) | (32ull << 32) | (1ull << 16);
__device__ __forceinline__ uint64_t make_desc128(uint32_t addr) {
    return DESC_BASE_SW128 | ((uint64_t)(addr >> 4) & 0x3FFF);
}
__device__ __forceinline__ uint64_t make_desc64(uint32_t addr) {
    return DESC_BASE_SW64 | ((uint64_t)(addr >> 4) & 0x3FFF);
}

#if TC_OK
// cg1 MMA (fallback)
__device__ __forceinline__ void mma_ss(uint32_t d, uint64_t a, uint64_t b,
                                       uint32_t idesc, bool en) {
    uint32_t e = en ? 1u : 0u;
    asm volatile(
        "{\n .reg .pred p;\n setp.ne.u32 p, %4, 0;\n"
        " tcgen05.mma.cta_group::1.kind::f16 [%0], %1, %2, %3, {%5,%5,%5,%5}, p;\n}"
        :: "r"(d), "l"(a), "l"(b), "r"(idesc), "r"(e), "r"(0u) : "memory");
}

// cg2 MMA: M=256 across the CTA pair, SS mode
__device__ __forceinline__ void mma_ss_cg2(uint32_t d, uint64_t a, uint64_t b,
                                           uint32_t idesc, bool en) {
    uint32_t e = en ? 1u : 0u;
    asm volatile(
        "{\n .reg .pred p;\n setp.ne.u32 p, %4, 0;\n"
        " tcgen05.mma.cta_group::2.kind::f16 [%0], %1, %2, %3, "
        "{%5,%5,%5,%5,%5,%5,%5,%5}, p;\n}"
        :: "r"(d), "l"(a), "l"(b), "r"(idesc), "r"(e), "r"(0u) : "memory");
}

// cg2 TMA 2D load: both CTAs execute; complete_tx targets the LEADER's barrier
__device__ __forceinline__ void tma2d_cg2(uint32_t dst, const CUtensorMap* map,
                                          int x, int y, uint32_t bar) {
    asm volatile(
        "{\n .reg .b32 lb;\n and.b32 lb, %4, 0xFEFFFFFF;\n"
        " cp.async.bulk.tensor.2d.cta_group::2.shared::cluster.global.tile"
        ".mbarrier::complete_tx::bytes [%0], [%1, {%2, %3}], [lb];\n}"
        :: "r"(dst), "l"(map), "r"(x), "r"(y), "r"(bar) : "memory");
}

#define TCG_ALLOC(sm, n) \
    asm volatile("tcgen05.alloc.cta_group::1.sync.aligned.shared::cta.b32 [%0], %1;" \
                 :: "r"(sm), "r"(n) : "memory")
#define TCG_DEALLOC(t, n) \
    asm volatile("tcgen05.dealloc.cta_group::1.sync.aligned.b32 %0, %1;" :: "r"(t), "r"(n))
#define TCG_RELINQ() \
    asm volatile("tcgen05.relinquish_alloc_permit.cta_group::1.sync.aligned;")
#define TCG_COMMIT(m) \
    asm volatile("tcgen05.commit.cta_group::1.mbarrier::arrive::one.shared::cluster.b64 [%0];" \
                 :: "r"(m) : "memory")

#define TCG_ALLOC_CG2(sm, n) \
    asm volatile("tcgen05.alloc.cta_group::2.sync.aligned.shared::cta.b32 [%0], %1;" \
                 :: "r"(sm), "r"(n) : "memory")
#define TCG_DEALLOC_CG2(t, n) \
    asm volatile("tcgen05.dealloc.cta_group::2.sync.aligned.b32 %0, %1;" :: "r"(t), "r"(n))
#define TCG_RELINQ_CG2() \
    asm volatile("tcgen05.relinquish_alloc_permit.cta_group::2.sync.aligned;")
#define TCG_COMMIT_CG2_MC(m, mask) \
    asm volatile("tcgen05.commit.cta_group::2.mbarrier::arrive::one.shared::cluster" \
                 ".multicast::cluster.b64 [%0], %1;" \
                 :: "r"(m), "h"((uint16_t)(mask)) : "memory")

#define TCG_FENCE_AFTER()  asm volatile("tcgen05.fence::after_thread_sync;" ::: "memory")
#define TCG_WAIT_LD()      asm volatile("tcgen05.wait::ld.sync.aligned;" ::: "memory")

#define TCG_LD_X32(r, ta) \
    asm volatile( \
        "tcgen05.ld.sync.aligned.32x32b.x32.b32 " \
        "{%0, %1, %2, %3, %4, %5, %6, %7, " \
        " %8, %9, %10, %11, %12, %13, %14, %15, " \
        " %16, %17, %18, %19, %20, %21, %22, %23, " \
        " %24, %25, %26, %27, %28, %29, %30, %31}, [%32];" \
        : "=r"((r)[0]),  "=r"((r)[1]),  "=r"((r)[2]),  "=r"((r)[3]), \
          "=r"((r)[4]),  "=r"((r)[5]),  "=r"((r)[6]),  "=r"((r)[7]), \
          "=r"((r)[8]),  "=r"((r)[9]),  "=r"((r)[10]), "=r"((r)[11]), \
          "=r"((r)[12]), "=r"((r)[13]), "=r"((r)[14]), "=r"((r)[15]), \
          "=r"((r)[16]), "=r"((r)[17]), "=r"((r)[18]), "=r"((r)[19]), \
          "=r"((r)[20]), "=r"((r)[21]), "=r"((r)[22]), "=r"((r)[23]), \
          "=r"((r)[24]), "=r"((r)[25]), "=r"((r)[26]), "=r"((r)[27]), \
          "=r"((r)[28]), "=r"((r)[29]), "=r"((r)[30]), "=r"((r)[31]) \
        : "r"(ta))
#endif // TC_OK

// ---------------------------------------------------------------------------
// fp32 -> bf16 hi/lo split helpers
// ---------------------------------------------------------------------------
__device__ __forceinline__ void split1(float x, bf16& h, bf16& l) {
    h = __float2bfloat16(x);
    l = __float2bfloat16(x - __bfloat162float(h));
}
__device__ __forceinline__ void pack4(float4 v, uint2& h, uint2& l) {
    bf16 h0, l0, h1, l1, h2, l2, h3, l3;
    split1(v.x, h0, l0); split1(v.y, h1, l1);
    split1(v.z, h2, l2); split1(v.w, h3, l3);
    h.x = ((uint32_t)__bfloat16_as_ushort(h1) << 16) | __bfloat16_as_ushort(h0);
    h.y = ((uint32_t)__bfloat16_as_ushort(h3) << 16) | __bfloat16_as_ushort(h2);
    l.x = ((uint32_t)__bfloat16_as_ushort(l1) << 16) | __bfloat16_as_ushort(l0);
    l.y = ((uint32_t)__bfloat16_as_ushort(l3) << 16) | __bfloat16_as_ushort(l2);
}

__global__ __launch_bounds__(256)
void split_kernel(const float4* __restrict__ in, uint2* __restrict__ hi,
                  uint2* __restrict__ lo, int n4)
{
    int i = blockIdx.x * 256 + threadIdx.x;
    if (i >= n4) return;
    float4 v = in[i];
    uint2 h, l;
    pack4(v, h, l);
    hi[i] = h;
    lo[i] = l;
}

__global__ __launch_bounds__(256)
void transpose_split_kernel(const float* __restrict__ E,
                            bf16* __restrict__ Th, bf16* __restrict__ Tl)
{
    __shared__ float t[32][33];
    const int b  = blockIdx.z;
    const int e0 = blockIdx.x << 5;
    const int h0 = blockIdx.y << 5;
    const int tx = threadIdx.x, ty = threadIdx.y;   // 32 x 8

    const float* src = E + (size_t)b * ENC * HDIM;
    #pragma unroll
    for (int r = 0; r < 32; r += 8)
        t[ty + r][tx] = src[(size_t)(e0 + ty + r) * HDIM + h0 + tx];
    __syncthreads();

    bf16* th = Th + (size_t)b * HDIM * ENC;
    bf16* tl = Tl + (size_t)b * HDIM * ENC;
    #pragma unroll
    for (int r = 0; r < 32; r += 8) {
        float x = t[tx][ty + r];
        bf16 h, l; split1(x, h, l);
        size_t o = (size_t)(h0 + ty + r) * ENC + e0 + tx;
        th[o] = h;
        tl[o] = l;
    }
}

// ---------------------------------------------------------------------------
// Shared GEMM constants
// ---------------------------------------------------------------------------
static constexpr uint32_t IDESC_BF16_M128_N256 =
    (1u << 4) | (1u << 7) | (1u << 10) | ((256u / 8u) << 17) | ((128u / 16u) << 24);
static constexpr uint32_t IDESC_BF16_M256_N256 =
    (1u << 4) | (1u << 7) | (1u << 10) | ((256u / 8u) << 17) | ((256u / 16u) << 24);

static constexpr int OFF_TMEMPTR = 0;
static constexpr int OFF_FULL    = 16;    // full[3]
static constexpr int OFF_MMA     = 64;    // mma[3]
static constexpr int OFF_MASK    = 1024;  // 256 floats
static constexpr int SMEM_STAGE0 = 2048;

// --- T2 cg2 engine: 2 M-tiles share B per K=32 stage (SW64), NBUF=3 ---
static constexpr int NBUF = 3;
static constexpr int T2_A0HI = 0,     T2_A0LO = 8192;
static constexpr int T2_A1HI = 16384, T2_A1LO = 24576;
static constexpr int T2_BHI  = 32768, T2_BLO  = 40960;
static constexpr int T2_BYTES = 49152;                  // 6 x 8KB per CTA
static constexpr int T2_SMEM  = SMEM_STAGE0 + NBUF * T2_BYTES;   // 149504

// --- fallback: cp.async cg1, 2 stages of K=64 (SW128) ---
static constexpr int OFF_AHI = 0, OFF_ALO = 16384, OFF_BHI = 32768, OFF_BLO = 65536;
static constexpr int STAGE_BYTES = 98304;
static constexpr int FB_SMEM     = SMEM_STAGE0 + 2 * STAGE_BYTES;   // 198656

// ---------------------------------------------------------------------------
// T2 cg2 GEMM: cluster(2,1) pair computes TWO 256x256 tiles (m0, m0+256)
// sharing the B tile per K-stage. Accumulators: tile0 = TMEM cols 0-255,
// tile1 = cols 256-511. Per-CTA delivered bytes per stage: 48 KB per 1536
// tensor-cyc = 32 B/cyc < ~42.6 B/cyc per-SM TMA cap.
//   grid: x = M/256 (2 CTAs = 1 pair per 512 M-rows; pair idx = x>>1),
//         y = N/256, z = batch
// ---------------------------------------------------------------------------
template<bool MASK>
__global__ __launch_bounds__(128, 1) __cluster_dims__(2, 1, 1)
void mma_gemm_t2(const __grid_constant__ CUtensorMap mapAhi,
                 const __grid_constant__ CUtensorMap mapAlo,
                 const __grid_constant__ CUtensorMap mapBhi,
                 const __grid_constant__ CUtensorMap mapBlo,
                 const float* __restrict__ Eg, float* __restrict__ Cg,
                 int M, int N, int K)
{
#if TC_OK
    extern __shared__ char smem[];
    const uint32_t sb = smem_u32(smem);
    const int tid = threadIdx.x;
    const int wid = tid >> 5, lid = tid & 31;
    const int b   = blockIdx.z;
    const int mB  = (blockIdx.x >> 1) * 512;   // PAIR tile base (both CTAs agree)
    const int nB  = blockIdx.y * 256;
    uint32_t rank;
    asm("mov.u32 %0, %%cluster_ctarank;" : "=r"(rank));
    const bool leader = (rank == 0);

    const int S = K / 32;

    if (wid == 0) TCG_ALLOC_CG2(sb + OFF_TMEMPTR, 512);
    if (tid == 0) {
        #pragma unroll
        for (int i = 0; i < NBUF; i++) {
            mbar_init(sb + OFF_FULL + 8 * i, 1);
            mbar_init(sb + OFF_MMA  + 8 * i, 1);
        }
    }
    __syncthreads();
    uint32_t tmem;
    asm volatile("ld.shared.b32 %0, [%1];" : "=r"(tmem) : "r"(sb + OFF_TMEMPTR));

    CLUSTER_SYNC_ALL();   // barriers visible before any cg2 TMA / commit

    const int aRow0 = b * M + mB + (int)rank * 128;        // tile0: own 128 rows
    const int aRow1 = aRow0 + 256;                         // tile1
    const int bRow  = b * N + nB + (int)rank * 128;        // B: own 128 n-rows

    if (wid == 1 && lid == 0) {
        // ---- producer (both CTAs): 6 local cg2 loads per stage ----
        uint32_t phm = 0u;
        for (int s = 0; s < S; s++) {
            const int buf = s % NBUF;
            if (s >= NBUF) {
                mbar_wait(sb + OFF_MMA + 8 * buf, (phm >> buf) & 1u);
                phm ^= 1u << buf;
            }
            const uint32_t st   = sb + SMEM_STAGE0 + buf * T2_BYTES;
            const uint32_t fbar = sb + OFF_FULL + 8 * buf;
            if (leader) mbar_expect(fbar, 2 * T2_BYTES);   // both CTAs' bytes
            const int k0 = s * 32;
            tma2d_cg2(st + T2_A0HI, &mapAhi, k0, aRow0, fbar);
            tma2d_cg2(st + T2_A0LO, &mapAlo, k0, aRow0, fbar);
            tma2d_cg2(st + T2_A1HI, &mapAhi, k0, aRow1, fbar);
            tma2d_cg2(st + T2_A1LO, &mapAlo, k0, aRow1, fbar);
            tma2d_cg2(st + T2_BHI,  &mapBhi, k0, bRow,  fbar);
            tma2d_cg2(st + T2_BLO,  &mapBlo, k0, bRow,  fbar);
        }
        for (int t = (S >= NBUF ? S - NBUF : 0); t < S; t++) {
            const int buf = t % NBUF;
            mbar_wait(sb + OFF_MMA + 8 * buf, (phm >> buf) & 1u);
            phm ^= 1u << buf;
        }
    } else if (wid == 0 && leader) {
        // ---- consumer: leader issues the pair MMAs for BOTH tiles ----
        uint32_t phf = 0u;
        for (int s = 0; s < S; s++) {
            const int buf = s % NBUF;
            mbar_wait(sb + OFF_FULL + 8 * buf, (phf >> buf) & 1u);
            phf ^= 1u << buf;
            if (elect_one()) {
                const uint32_t st = sb + SMEM_STAGE0 + buf * T2_BYTES;
                uint64_t da0h = make_desc64(st + T2_A0HI);
                uint64_t da0l = make_desc64(st + T2_A0LO);
                uint64_t da1h = make_desc64(st + T2_A1HI);
                uint64_t da1l = make_desc64(st + T2_A1LO);
                uint64_t dbh  = make_desc64(st + T2_BHI);
                uint64_t dbl  = make_desc64(st + T2_BLO);
                #pragma unroll
                for (int k = 0; k < 2; k++) {   // two K=16 chunks per 64B row
                    bool en0 = !(s == 0 && k == 0);
                    // tile0 -> TMEM cols 0..255
                    mma_ss_cg2(tmem,       da0h + 2*k, dbh + 2*k, IDESC_BF16_M256_N256, en0);
                    mma_ss_cg2(tmem,       da0h + 2*k, dbl + 2*k, IDESC_BF16_M256_N256, true);
                    mma_ss_cg2(tmem,       da0l + 2*k, dbh + 2*k, IDESC_BF16_M256_N256, true);
                    // tile1 -> TMEM cols 256..511
                    mma_ss_cg2(tmem + 256, da1h + 2*k, dbh + 2*k, IDESC_BF16_M256_N256, en0);
                    mma_ss_cg2(tmem + 256, da1h + 2*k, dbl + 2*k, IDESC_BF16_M256_N256, true);
                    mma_ss_cg2(tmem + 256, da1l + 2*k, dbh + 2*k, IDESC_BF16_M256_N256, true);
                }
                TCG_COMMIT_CG2_MC(sb + OFF_MMA + 8 * buf, 0x3);
            }
        }
    }

    __syncthreads();      // producers verified all commits landed
    TCG_FENCE_AFTER();

    // pad mask (scores only)
    float* mS = (float*)(smem + OFF_MASK);
    if (MASK) {
        for (int i = tid; i < 256; i += 128)
            mS[i] = (Eg[((size_t)b * N + nB + i) * HDIM] == 0.0f) ? 1.0f : 0.0f;
        __syncthreads();
    }

    // epilogue: two tiles; this CTA's TMEM holds its own 128 rows x 256 cols each
    #pragma unroll
    for (int t = 0; t < 2; t++) {
        const int row = mB + t * 256 + (int)rank * 128 + wid * 32 + lid;
        float* crow = Cg + ((size_t)b * M + row) * N + nB;
        for (int cc = 0; cc < 8; cc++) {
            uint32_t r[32];
            TCG_LD_X32(r, tmem + t * 256 + cc * 32);
            TCG_WAIT_LD();
            #pragma unroll
            for (int j = 0; j < 32; j += 4) {
                float4 v;
                v.x = __uint_as_float(r[j + 0]);
                v.y = __uint_as_float(r[j + 1]);
                v.z = __uint_as_float(r[j + 2]);
                v.w = __uint_as_float(r[j + 3]);
                if (MASK) {
                    if (mS[cc * 32 + j + 0] != 0.0f) v.x = -CUDART_INF_F;
                    if (mS[cc * 32 + j + 1] != 0.0f) v.y = -CUDART_INF_F;
                    if (mS[cc * 32 + j + 2] != 0.0f) v.z = -CUDART_INF_F;
                    if (mS[cc * 32 + j + 3] != 0.0f) v.w = -CUDART_INF_F;
                }
                *reinterpret_cast<float4*>(crow + cc * 32 + j) = v;
            }
        }
    }

    __syncthreads();
    if (wid == 0) {
        TCG_RELINQ_CG2();
        TCG_DEALLOC_CG2(tmem, 512);
    }
    CLUSTER_SYNC_ALL();   // no CTA exits while the pair MMA may read its smem
#endif // TC_OK
}

// ---------------------------------------------------------------------------
// FALLBACK: cp.async cg1 GEMM (used only if tensormap encode is unavailable)
// ---------------------------------------------------------------------------
__device__ __forceinline__ void load_tile(uint32_t sdst, const bf16* g,
                                          int rows, int ldk, int tid)
{
    for (int idx = tid; idx < rows * 8; idx += 128) {
        int r = idx >> 3, seg = idx & 7;
        uint32_t bo = (uint32_t)(r * 128 + seg * 16);
        cpasync16(sdst + SWZ128(bo), g + (size_t)r * ldk + seg * 8);
    }
}

template<bool MASK>
__global__ __launch_bounds__(128)
void mma_gemm_fb(const bf16* __restrict__ Ahi, const bf16* __restrict__ Alo,
                 const bf16* __restrict__ Bhi, const bf16* __restrict__ Blo,
                 const float* __restrict__ Eg, float* __restrict__ Cg,
                 int M, int N, int K)
{
#if TC_OK
    extern __shared__ char smem[];
    const uint32_t sb  = smem_u32(smem);
    const int tid = threadIdx.x;
    const int wid = tid >> 5, lid = tid & 31;
    const int b   = blockIdx.z;
    const int mB  = blockIdx.y * 128;
    const int nB  = blockIdx.x * 256;

    const bf16* aH = Ahi + ((size_t)b * M + mB) * K;
    const bf16* aL = Alo + ((size_t)b * M + mB) * K;
    const bf16* bH = Bhi + ((size_t)b * N + nB) * K;
    const bf16* bL = Blo + ((size_t)b * N + nB) * K;

    if (wid == 0) TCG_ALLOC(sb + OFF_TMEMPTR, 256);
    if (tid == 0) {
        mbar_init(sb + OFF_MMA, 1);
        mbar_init(sb + OFF_MMA + 8, 1);
    }
    __syncthreads();
    uint32_t tmem;
    asm volatile("ld.shared.b32 %0, [%1];" : "=r"(tmem) : "r"(sb + OFF_TMEMPTR));

    const int S = K / 64;
    {
        uint32_t st = sb + SMEM_STAGE0;
        load_tile(st + OFF_AHI, aH, 128, K, tid);
        load_tile(st + OFF_ALO, aL, 128, K, tid);
        load_tile(st + OFF_BHI, bH, 256, K, tid);
        load_tile(st + OFF_BLO, bL, 256, K, tid);
        asm volatile("cp.async.commit_group;" ::: "memory");
    }
    uint32_t ph[2] = {0u, 0u};
    for (int s = 0; s < S; s++) {
        const int buf  = s & 1;
        const int nbuf = buf ^ 1;
        if (s + 1 < S) {
            if (s >= 1) {
                mbar_wait(sb + OFF_MMA + 8 * nbuf, ph[nbuf]);
                ph[nbuf] ^= 1;
            }
            const int k0 = (s + 1) * 64;
            uint32_t st = sb + SMEM_STAGE0 + nbuf * STAGE_BYTES;
            load_tile(st + OFF_AHI, aH + k0, 128, K, tid);
            load_tile(st + OFF_ALO, aL + k0, 128, K, tid);
            load_tile(st + OFF_BHI, bH + k0, 256, K, tid);
            load_tile(st + OFF_BLO, bL + k0, 256, K, tid);
            asm volatile("cp.async.commit_group;" ::: "memory");
            asm volatile("cp.async.wait_group 1;" ::: "memory");
        } else {
            asm volatile("cp.async.wait_group 0;" ::: "memory");
        }
        __syncthreads();
        if (wid == 0) {
            asm volatile("fence.proxy.async.shared::cta;" ::: "memory");
            if (elect_one()) {
                uint32_t st = sb + SMEM_STAGE0 + buf * STAGE_BYTES;
                uint64_t dah = make_desc128(st + OFF_AHI);
                uint64_t dal = make_desc128(st + OFF_ALO);
                uint64_t dbh = make_desc128(st + OFF_BHI);
                uint64_t dbl = make_desc128(st + OFF_BLO);
                #pragma unroll
                for (int k = 0; k < 4; k++) {
                    bool en0 = !(s == 0 && k == 0);
                    mma_ss(tmem, dah + 2 * k, dbh + 2 * k, IDESC_BF16_M128_N256, en0);
                    mma_ss(tmem, dah + 2 * k, dbl + 2 * k, IDESC_BF16_M128_N256, true);
                    mma_ss(tmem, dal + 2 * k, dbh + 2 * k, IDESC_BF16_M128_N256, true);
                }
                TCG_COMMIT(sb + OFF_MMA + 8 * buf);
            }
        }
    }
    const int lb = (S - 1) & 1;
    mbar_wait(sb + OFF_MMA + 8 * lb, ph[lb]);
    TCG_FENCE_AFTER();

    float* mS = (float*)(smem + OFF_MASK);
    if (MASK) {
        for (int i = tid; i < 256; i += 128)
            mS[i] = (Eg[((size_t)b * N + nB + i) * HDIM] == 0.0f) ? 1.0f : 0.0f;
    }
    __syncthreads();

    const int row = mB + wid * 32 + lid;
    float* crow = Cg + ((size_t)b * M + row) * N + nB;
    for (int cc = 0; cc < 8; cc++) {
        uint32_t r[32];
        TCG_LD_X32(r, tmem + cc * 32);
        TCG_WAIT_LD();
        #pragma unroll
        for (int j = 0; j < 32; j += 4) {
            float4 v;
            v.x = __uint_as_float(r[j + 0]);
            v.y = __uint_as_float(r[j + 1]);
            v.z = __uint_as_float(r[j + 2]);
            v.w = __uint_as_float(r[j + 3]);
            if (MASK) {
                if (mS[cc * 32 + j + 0] != 0.0f) v.x = -CUDART_INF_F;
                if (mS[cc * 32 + j + 1] != 0.0f) v.y = -CUDART_INF_F;
                if (mS[cc * 32 + j + 2] != 0.0f) v.z = -CUDART_INF_F;
                if (mS[cc * 32 + j + 3] != 0.0f) v.w = -CUDART_INF_F;
            }
            *reinterpret_cast<float4*>(crow + cc * 32 + j) = v;
        }
    }
    __syncthreads();
    if (wid == 0) {
        TCG_RELINQ();
        TCG_DEALLOC(tmem, 256);
    }
#endif // TC_OK
}

// ---------------------------------------------------------------------------
// Row softmax (2048), in place, also emits P hi/lo bf16.
// ---------------------------------------------------------------------------
__inline__ __device__ float warpMax(float v) {
    #pragma unroll
    for (int o = 16; o > 0; o >>= 1) v = fmaxf(v, __shfl_xor_sync(0xffffffffu, v, o));
    return v;
}
__inline__ __device__ float warpSum(float v) {
    #pragma unroll
    for (int o = 16; o > 0; o >>= 1) v += __shfl_xor_sync(0xffffffffu, v, o);
    return v;
}

__global__ __launch_bounds__(256)
void softmax_split_kernel(float* __restrict__ attn,
                          bf16* __restrict__ Phi, bf16* __restrict__ Plo)
{
    const size_t row = blockIdx.x;
    float* p = attn + row * (size_t)ENC;
    const int tid = threadIdx.x;

    float4 v0 = reinterpret_cast<float4*>(p)[tid];
    float4 v1 = reinterpret_cast<float4*>(p)[tid + 256];

    __shared__ float smax[8];
    __shared__ float ssum[8];

    float m = fmaxf(fmaxf(fmaxf(v0.x, v0.y), fmaxf(v0.z, v0.w)),
                    fmaxf(fmaxf(v1.x, v1.y), fmaxf(v1.z, v1.w)));
    float wm = warpMax(m);
    if ((tid & 31) == 0) smax[tid >> 5] = wm;
    __syncthreads();
    if (tid < 32) {
        float t = (tid < 8) ? smax[tid] : -CUDART_INF_F;
        t = warpMax(t);
        if (tid == 0) smax[0] = t;
    }
    __syncthreads();
    const float bm = smax[0];

    v0.x = __expf(v0.x - bm); v0.y = __expf(v0.y - bm);
    v0.z = __expf(v0.z - bm); v0.w = __expf(v0.w - bm);
    v1.x = __expf(v1.x - bm); v1.y = __expf(v1.y - bm);
    v1.z = __expf(v1.z - bm); v1.w = __expf(v1.w - bm);

    float s = (v0.x + v0.y + v0.z + v0.w) + (v1.x + v1.y + v1.z + v1.w);
    float ws = warpSum(s);
    if ((tid & 31) == 0) ssum[tid >> 5] = ws;
    __syncthreads();
    if (tid < 32) {
        float t = (tid < 8) ? ssum[tid] : 0.0f;
        t = warpSum(t);
        if (tid == 0) ssum[0] = t;
    }
    __syncthreads();
    const float inv = 1.0f / ssum[0];

    v0.x *= inv; v0.y *= inv; v0.z *= inv; v0.w *= inv;
    v1.x *= inv; v1.y *= inv; v1.z *= inv; v1.w *= inv;

    reinterpret_cast<float4*>(p)[tid]       = v0;
    reinterpret_cast<float4*>(p)[tid + 256] = v1;

    uint2 h0, l0, h1, l1;
    pack4(v0, h0, l0);
    pack4(v1, h1, l1);
    uint2* ph = reinterpret_cast<uint2*>(Phi + row * (size_t)ENC);
    uint2* pl = reinterpret_cast<uint2*>(Plo + row * (size_t)ENC);
    ph[tid]       = h0;  ph[tid + 256] = h1;
    pl[tid]       = l0;  pl[tid + 256] = l1;
}

// ---------------------------------------------------------------------------
// Host
// ---------------------------------------------------------------------------
typedef CUresult (*EncodeFn)(
    CUtensorMap*, CUtensorMapDataType, cuuint32_t, void*,
    const cuuint64_t*, const cuuint64_t*, const cuuint32_t*, const cuuint32_t*,
    CUtensorMapInterleave, CUtensorMapSwizzle, CUtensorMapL2promotion,
    CUtensorMapFloatOOBfill);

static bool encode_sw64(EncodeFn fn, CUtensorMap* m, void* base,
                        uint64_t kdim, uint64_t rows)
{
    cuuint64_t dims[2]    = {kdim, rows};
    cuuint64_t strides[1] = {kdim * 2};
    cuuint32_t box[2]     = {32u, 128u};          // 32 bf16 = 64B (SW64), 128 rows
    cuuint32_t estr[2]    = {1u, 1u};
    CUresult r = fn(m, CU_TENSOR_MAP_DATA_TYPE_BFLOAT16, 2, base,
                    dims, strides, box, estr,
                    CU_TENSOR_MAP_INTERLEAVE_NONE, CU_TENSOR_MAP_SWIZZLE_64B,
                    CU_TENSOR_MAP_L2_PROMOTION_L2_128B,
                    CU_TENSOR_MAP_FLOAT_OOB_FILL_NONE);
    return r == CUDA_SUCCESS;
}

extern "C" void kernel_launch(void* const* d_in, const int* in_sizes, int n_in,
                              void* d_out, int out_size)
{
    const float* D = (const float*)d_in[0];
    const float* E = (const float*)d_in[1];

    float* ctx  = (float*)d_out;                        // [16,2048,1024]
    float* attn = ctx + (size_t)BATCH * DEC * HDIM;     // [16,2048,2048]

    void *pDhi, *pDlo, *pEhi, *pElo, *pEThi, *pETlo, *pPhi, *pPlo;
    cudaGetSymbolAddress(&pDhi,  g_Dhi);
    cudaGetSymbolAddress(&pDlo,  g_Dlo);
    cudaGetSymbolAddress(&pEhi,  g_Ehi);
    cudaGetSymbolAddress(&pElo,  g_Elo);
    cudaGetSymbolAddress(&pEThi, g_EThi);
    cudaGetSymbolAddress(&pETlo, g_ETlo);
    cudaGetSymbolAddress(&pPhi,  g_Phi);
    cudaGetSymbolAddress(&pPlo,  g_Plo);

    cudaFuncSetAttribute(mma_gemm_t2<true>,
                         cudaFuncAttributeMaxDynamicSharedMemorySize, T2_SMEM);
    cudaFuncSetAttribute(mma_gemm_t2<false>,
                         cudaFuncAttributeMaxDynamicSharedMemorySize, T2_SMEM);
    cudaFuncSetAttribute(mma_gemm_fb<true>,
                         cudaFuncAttributeMaxDynamicSharedMemorySize, FB_SMEM);
    cudaFuncSetAttribute(mma_gemm_fb<false>,
                         cudaFuncAttributeMaxDynamicSharedMemorySize, FB_SMEM);

    EncodeFn enc = nullptr;
    {
        void* fp = nullptr;
        cudaDriverEntryPointQueryResult qr = cudaDriverEntryPointSymbolNotFound;
        if (cudaGetDriverEntryPoint("cuTensorMapEncodeTiled", &fp,
                                    cudaEnableDefault, &qr) == cudaSuccess &&
            qr == cudaDriverEntryPointSuccess)
            enc = (EncodeFn)fp;
    }

    CUtensorMap mDhi, mDlo, mEhi, mElo, mPhi, mPlo, mEThi, mETlo;
    bool tma_ok = (enc != nullptr);
    if (tma_ok) {
        tma_ok =
            encode_sw64(enc, &mDhi,  pDhi,  HDIM, (uint64_t)BATCH * DEC)  &&
            encode_sw64(enc, &mDlo,  pDlo,  HDIM, (uint64_t)BATCH * DEC)  &&
            encode_sw64(enc, &mEhi,  pEhi,  HDIM, (uint64_t)BATCH * ENC)  &&
            encode_sw64(enc, &mElo,  pElo,  HDIM, (uint64_t)BATCH * ENC)  &&
            encode_sw64(enc, &mPhi,  pPhi,  ENC,  (uint64_t)BATCH * DEC)  &&
            encode_sw64(enc, &mPlo,  pPlo,  ENC,  (uint64_t)BATCH * DEC)  &&
            encode_sw64(enc, &mEThi, pEThi, ENC,  (uint64_t)BATCH * HDIM) &&
            encode_sw64(enc, &mETlo, pETlo, ENC,  (uint64_t)BATCH * HDIM);
    }

    const int n4 = BATCH * DEC * HDIM / 4;
    split_kernel<<<n4 / 256, 256>>>((const float4*)D, (uint2*)pDhi, (uint2*)pDlo, n4);
    split_kernel<<<n4 / 256, 256>>>((const float4*)E, (uint2*)pEhi, (uint2*)pElo, n4);

    transpose_split_kernel<<<dim3(ENC / 32, HDIM / 32, BATCH), dim3(32, 8)>>>(
        E, (bf16*)pEThi, (bf16*)pETlo);

    if (tma_ok) {
        // scores: M=DEC, N=ENC, K=HDIM; grid x = M/256 (pairs of CTAs), y = N/256
        mma_gemm_t2<true><<<dim3(DEC / 256, ENC / 256, BATCH), 128, T2_SMEM>>>(
            mDhi, mDlo, mEhi, mElo, E, attn, DEC, ENC, HDIM);
    } else {
        mma_gemm_fb<true><<<dim3(ENC / 256, DEC / 128, BATCH), 128, FB_SMEM>>>(
            (const bf16*)pDhi, (const bf16*)pDlo,
            (const bf16*)pEhi, (const bf16*)pElo, E, attn, DEC, ENC, HDIM);
    }

    softmax_split_kernel<<<BATCH * DEC, 256>>>(attn, (bf16*)pPhi, (bf16*)pPlo);

    if (tma_ok) {
        // context: M=DEC, N=HDIM, K=ENC; grid x = M/256, y = N/256
        mma_gemm_t2<false><<<dim3(DEC / 256, HDIM / 256, BATCH), 128, T2_SMEM>>>(
            mPhi, mPlo, mEThi, mETlo, nullptr, ctx, DEC, HDIM, ENC);
    } else {
        mma_gemm_fb<false><<<dim3(HDIM / 256, DEC / 128, BATCH), 128, FB_SMEM>>>(
            (const bf16*)pPhi, (const bf16*)pPlo,
            (const bf16*)pEThi, (const bf16*)pETlo, nullptr, ctx, DEC, HDIM, ENC);
    }
}

// round 16
// speedup vs baseline: 1.0255x; 1.0255x over previous
#include <cuda_runtime.h>
#include <cuda.h>
#include <cuda_bf16.h>
#include <math_constants.h>
#include <cstdint>

#define BATCH 16
#define DEC   2048
#define ENC   2048
#define HDIM  1024

#if defined(__CUDA_ARCH_SPECIFIC__) || defined(__CUDA_ARCH_FEAT_SM103_ALL) || defined(__CUDA_ARCH_FEAT_SM100_ALL)
#define TC_OK 1
#else
#define TC_OK 0
#endif

typedef __nv_bfloat16 bf16;

// ---------------------------------------------------------------------------
// Scratch (static device globals)
// ---------------------------------------------------------------------------
__device__ bf16 g_Dhi [(size_t)BATCH * DEC  * HDIM];
__device__ bf16 g_Dlo [(size_t)BATCH * DEC  * HDIM];
__device__ bf16 g_Ehi [(size_t)BATCH * ENC  * HDIM];
__device__ bf16 g_Elo [(size_t)BATCH * ENC  * HDIM];
__device__ bf16 g_EThi[(size_t)BATCH * HDIM * ENC ];
__device__ bf16 g_ETlo[(size_t)BATCH * HDIM * ENC ];
__device__ bf16 g_Phi [(size_t)BATCH * DEC  * ENC ];
__device__ bf16 g_Plo [(size_t)BATCH * DEC  * ENC ];

// ---------------------------------------------------------------------------
// PTX helpers
// ---------------------------------------------------------------------------
__device__ __forceinline__ uint32_t smem_u32(const void* p) {
    uint32_t a;
    asm("{ .reg .u64 t; cvta.to.shared.u64 t, %1; cvt.u32.u64 %0, t; }"
        : "=r"(a) : "l"(p));
    return a;
}

__device__ __forceinline__ bool elect_one() {
    uint32_t p;
    asm volatile("{\n .reg .pred p;\n elect.sync _|p, 0xFFFFFFFF;\n"
                 " selp.b32 %0, 1, 0, p;\n}" : "=r"(p));
    return p != 0;
}

#define SWZ128(b) ((b) ^ (((b) >> 3) & 0x70))

__device__ __forceinline__ void cpasync16(uint32_t s, const void* g) {
    asm volatile("cp.async.cg.shared.global [%0], [%1], 16;"
                 :: "r"(s), "l"(g) : "memory");
}

__device__ __forceinline__ void mbar_init(uint32_t m, uint32_t cnt) {
    asm volatile("mbarrier.init.shared.b64 [%0], %1;" :: "r"(m), "r"(cnt) : "memory");
}

__device__ __forceinline__ void mbar_expect(uint32_t m, uint32_t tx) {
    asm volatile("mbarrier.arrive.expect_tx.shared.b64 _, [%0], %1;"
                 :: "r"(m), "r"(tx) : "memory");
}

__device__ __forceinline__ void mbar_wait(uint32_t m, uint32_t phase) {
    asm volatile(
        "{\n .reg .pred P;\n"
        "LAB%=:\n"
        " mbarrier.try_wait.parity.acquire.cta.shared::cta.b64 P, [%0], %1, 0x989680;\n"
        " @P bra DONE%=;\n"
        " bra LAB%=;\n"
        "DONE%=:\n}"
        :: "r"(m), "r"(phase) : "memory");
}

#define CLUSTER_SYNC_ALL() do { \
    asm volatile("barrier.cluster.arrive.aligned;" ::: "memory"); \
    asm volatile("barrier.cluster.wait.aligned;"   ::: "memory"); \
} while (0)

// K-major SMEM descriptors (Blackwell, version=1)
static constexpr uint64_t DESC_BASE_SW128 =
    (2ull << 61) | (1ull << 46) | (64ull << 32) | (1ull << 16);
static constexpr uint64_t DESC_BASE_SW64 =
    (4ull << 61) | (1ull << 46) | (32ull << 32) | (1ull << 16);
__device__ __forceinline__ uint64_t make_desc128(uint32_t addr) {
    return DESC_BASE_SW128 | ((uint64_t)(addr >> 4) & 0x3FFF);
}
__device__ __forceinline__ uint64_t make_desc64(uint32_t addr) {
    return DESC_BASE_SW64 | ((uint64_t)(addr >> 4) & 0x3FFF);
}

#if TC_OK
// cg1 MMA (fallback)
__device__ __forceinline__ void mma_ss(uint32_t d, uint64_t a, uint64_t b,
                                       uint32_t idesc, bool en) {
    uint32_t e = en ? 1u : 0u;
    asm volatile(
        "{\n .reg .pred p;\n setp.ne.u32 p, %4, 0;\n"
        " tcgen05.mma.cta_group::1.kind::f16 [%0], %1, %2, %3, {%5,%5,%5,%5}, p;\n}"
        :: "r"(d), "l"(a), "l"(b), "r"(idesc), "r"(e), "r"(0u) : "memory");
}

// cg2 MMA: M=256 across the CTA pair, SS mode
__device__ __forceinline__ void mma_ss_cg2(uint32_t d, uint64_t a, uint64_t b,
                                           uint32_t idesc, bool en) {
    uint32_t e = en ? 1u : 0u;
    asm volatile(
        "{\n .reg .pred p;\n setp.ne.u32 p, %4, 0;\n"
        " tcgen05.mma.cta_group::2.kind::f16 [%0], %1, %2, %3, "
        "{%5,%5,%5,%5,%5,%5,%5,%5}, p;\n}"
        :: "r"(d), "l"(a), "l"(b), "r"(idesc), "r"(e), "r"(0u) : "memory");
}

// cg2 TMA 2D load: both CTAs execute; complete_tx targets the LEADER's barrier
__device__ __forceinline__ void tma2d_cg2(uint32_t dst, const CUtensorMap* map,
                                          int x, int y, uint32_t bar) {
    asm volatile(
        "{\n .reg .b32 lb;\n and.b32 lb, %4, 0xFEFFFFFF;\n"
        " cp.async.bulk.tensor.2d.cta_group::2.shared::cluster.global.tile"
        ".mbarrier::complete_tx::bytes [%0], [%1, {%2, %3}], [lb];\n}"
        :: "r"(dst), "l"(map), "r"(x), "r"(y), "r"(bar) : "memory");
}

#define TCG_ALLOC(sm, n) \
    asm volatile("tcgen05.alloc.cta_group::1.sync.aligned.shared::cta.b32 [%0], %1;" \
                 :: "r"(sm), "r"(n) : "memory")
#define TCG_DEALLOC(t, n) \
    asm volatile("tcgen05.dealloc.cta_group::1.sync.aligned.b32 %0, %1;" :: "r"(t), "r"(n))
#define TCG_RELINQ() \
    asm volatile("tcgen05.relinquish_alloc_permit.cta_group::1.sync.aligned;")
#define TCG_COMMIT(m) \
    asm volatile("tcgen05.commit.cta_group::1.mbarrier::arrive::one.shared::cluster.b64 [%0];" \
                 :: "r"(m) : "memory")

#define TCG_ALLOC_CG2(sm, n) \
    asm volatile("tcgen05.alloc.cta_group::2.sync.aligned.shared::cta.b32 [%0], %1;" \
                 :: "r"(sm), "r"(n) : "memory")
#define TCG_DEALLOC_CG2(t, n) \
    asm volatile("tcgen05.dealloc.cta_group::2.sync.aligned.b32 %0, %1;" :: "r"(t), "r"(n))
#define TCG_RELINQ_CG2() \
    asm volatile("tcgen05.relinquish_alloc_permit.cta_group::2.sync.aligned;")
#define TCG_COMMIT_CG2_MC(m, mask) \
    asm volatile("tcgen05.commit.cta_group::2.mbarrier::arrive::one.shared::cluster" \
                 ".multicast::cluster.b64 [%0], %1;" \
                 :: "r"(m), "h"((uint16_t)(mask)) : "memory")

#define TCG_FENCE_AFTER()  asm volatile("tcgen05.fence::after_thread_sync;" ::: "memory")
#define TCG_WAIT_LD()      asm volatile("tcgen05.wait::ld.sync.aligned;" ::: "memory")

#define TCG_LD_X32(r, ta) \
    asm volatile( \
        "tcgen05.ld.sync.aligned.32x32b.x32.b32 " \
        "{%0, %1, %2, %3, %4, %5, %6, %7, " \
        " %8, %9, %10, %11, %12, %13, %14, %15, " \
        " %16, %17, %18, %19, %20, %21, %22, %23, " \
        " %24, %25, %26, %27, %28, %29, %30, %31}, [%32];" \
        : "=r"((r)[0]),  "=r"((r)[1]),  "=r"((r)[2]),  "=r"((r)[3]), \
          "=r"((r)[4]),  "=r"((r)[5]),  "=r"((r)[6]),  "=r"((r)[7]), \
          "=r"((r)[8]),  "=r"((r)[9]),  "=r"((r)[10]), "=r"((r)[11]), \
          "=r"((r)[12]), "=r"((r)[13]), "=r"((r)[14]), "=r"((r)[15]), \
          "=r"((r)[16]), "=r"((r)[17]), "=r"((r)[18]), "=r"((r)[19]), \
          "=r"((r)[20]), "=r"((r)[21]), "=r"((r)[22]), "=r"((r)[23]), \
          "=r"((r)[24]), "=r"((r)[25]), "=r"((r)[26]), "=r"((r)[27]), \
          "=r"((r)[28]), "=r"((r)[29]), "=r"((r)[30]), "=r"((r)[31]) \
        : "r"(ta))
#endif // TC_OK

// ---------------------------------------------------------------------------
// fp32 -> bf16 hi/lo split helpers
// ---------------------------------------------------------------------------
__device__ __forceinline__ void split1(float x, bf16& h, bf16& l) {
    h = __float2bfloat16(x);
    l = __float2bfloat16(x - __bfloat162float(h));
}
__device__ __forceinline__ void pack4(float4 v, uint2& h, uint2& l) {
    bf16 h0, l0, h1, l1, h2, l2, h3, l3;
    split1(v.x, h0, l0); split1(v.y, h1, l1);
    split1(v.z, h2, l2); split1(v.w, h3, l3);
    h.x = ((uint32_t)__bfloat16_as_ushort(h1) << 16) | __bfloat16_as_ushort(h0);
    h.y = ((uint32_t)__bfloat16_as_ushort(h3) << 16) | __bfloat16_as_ushort(h2);
    l.x = ((uint32_t)__bfloat16_as_ushort(l1) << 16) | __bfloat16_as_ushort(l0);
    l.y = ((uint32_t)__bfloat16_as_ushort(l3) << 16) | __bfloat16_as_ushort(l2);
}

__global__ __launch_bounds__(256)
void split_kernel(const float4* __restrict__ in, uint2* __restrict__ hi,
                  uint2* __restrict__ lo, int n4)
{
    int i = blockIdx.x * 256 + threadIdx.x;
    if (i >= n4) return;
    float4 v = in[i];
    uint2 h, l;
    pack4(v, h, l);
    hi[i] = h;
    lo[i] = l;
}

__global__ __launch_bounds__(256)
void transpose_split_kernel(const float* __restrict__ E,
                            bf16* __restrict__ Th, bf16* __restrict__ Tl)
{
    __shared__ float t[32][33];
    const int b  = blockIdx.z;
    const int e0 = blockIdx.x << 5;
    const int h0 = blockIdx.y << 5;
    const int tx = threadIdx.x, ty = threadIdx.y;   // 32 x 8

    const float* src = E + (size_t)b * ENC * HDIM;
    #pragma unroll
    for (int r = 0; r < 32; r += 8)
        t[ty + r][tx] = src[(size_t)(e0 + ty + r) * HDIM + h0 + tx];
    __syncthreads();

    bf16* th = Th + (size_t)b * HDIM * ENC;
    bf16* tl = Tl + (size_t)b * HDIM * ENC;
    #pragma unroll
    for (int r = 0; r < 32; r += 8) {
        float x = t[tx][ty + r];
        bf16 h, l; split1(x, h, l);
        size_t o = (size_t)(h0 + ty + r) * ENC + e0 + tx;
        th[o] = h;
        tl[o] = l;
    }
}

// ---------------------------------------------------------------------------
// Shared GEMM constants
// ---------------------------------------------------------------------------
static constexpr uint32_t IDESC_BF16_M128_N256 =
    (1u << 4) | (1u << 7) | (1u << 10) | ((256u / 8u) << 17) | ((128u / 16u) << 24);
static constexpr uint32_t IDESC_BF16_M256_N256 =
    (1u << 4) | (1u << 7) | (1u << 10) | ((256u / 8u) << 17) | ((256u / 16u) << 24);

static constexpr int OFF_TMEMPTR = 0;
static constexpr int OFF_FULL    = 16;    // full[3]
static constexpr int OFF_MMA     = 64;    // mma[3]
static constexpr int OFF_MASK    = 1024;  // 256 floats
static constexpr int SMEM_STAGE0 = 2048;

// --- SCORES engine (R15 T2): 2 M-tiles share B per K=32 stage (SW64), NBUF=3 ---
static constexpr int NBUF = 3;
static constexpr int T2_A0HI = 0,     T2_A0LO = 8192;
static constexpr int T2_A1HI = 16384, T2_A1LO = 24576;
static constexpr int T2_BHI  = 32768, T2_BLO  = 40960;
static constexpr int T2_BYTES = 49152;                  // 6 x 8KB per CTA
static constexpr int T2_SMEM  = SMEM_STAGE0 + NBUF * T2_BYTES;   // 149504

// --- CONTEXT engine (R13): cg2 pair 256x256, K=64 (SW128), NBUF=3 ---
static constexpr int CG_AHI = 0, CG_ALO = 16384, CG_BHI = 32768, CG_BLO = 49152;
static constexpr int CG_BYTES = 65536;   // 4 x 16KB (128 rows x 128B)
static constexpr int CG_SMEM  = SMEM_STAGE0 + NBUF * CG_BYTES;   // 198656

// --- fallback: cp.async cg1, 2 stages of K=64 (SW128) ---
static constexpr int OFF_AHI = 0, OFF_ALO = 16384, OFF_BHI = 32768, OFF_BLO = 65536;
static constexpr int STAGE_BYTES = 98304;
static constexpr int FB_SMEM     = SMEM_STAGE0 + 2 * STAGE_BYTES;   // 198656

// ---------------------------------------------------------------------------
// SCORES: T2 cg2 GEMM — cluster(2,1) pair computes TWO 256x256 tiles sharing
// B per K=32 stage. TMEM: tile0 = cols 0-255, tile1 = cols 256-511.
//   grid: x = M/256 (pair idx = x>>1), y = N/256, z = batch
// ---------------------------------------------------------------------------
__global__ __launch_bounds__(128, 1) __cluster_dims__(2, 1, 1)
void scores_t2(const __grid_constant__ CUtensorMap mapAhi,
               const __grid_constant__ CUtensorMap mapAlo,
               const __grid_constant__ CUtensorMap mapBhi,
               const __grid_constant__ CUtensorMap mapBlo,
               const float* __restrict__ Eg, float* __restrict__ Cg,
               int M, int N, int K)
{
#if TC_OK
    extern __shared__ char smem[];
    const uint32_t sb = smem_u32(smem);
    const int tid = threadIdx.x;
    const int wid = tid >> 5, lid = tid & 31;
    const int b   = blockIdx.z;
    const int mB  = (blockIdx.x >> 1) * 512;   // PAIR tile base
    const int nB  = blockIdx.y * 256;
    uint32_t rank;
    asm("mov.u32 %0, %%cluster_ctarank;" : "=r"(rank));
    const bool leader = (rank == 0);

    const int S = K / 32;

    if (wid == 0) TCG_ALLOC_CG2(sb + OFF_TMEMPTR, 512);
    if (tid == 0) {
        #pragma unroll
        for (int i = 0; i < NBUF; i++) {
            mbar_init(sb + OFF_FULL + 8 * i, 1);
            mbar_init(sb + OFF_MMA  + 8 * i, 1);
        }
    }
    __syncthreads();
    uint32_t tmem;
    asm volatile("ld.shared.b32 %0, [%1];" : "=r"(tmem) : "r"(sb + OFF_TMEMPTR));

    CLUSTER_SYNC_ALL();

    const int aRow0 = b * M + mB + (int)rank * 128;
    const int aRow1 = aRow0 + 256;
    const int bRow  = b * N + nB + (int)rank * 128;

    if (wid == 1 && lid == 0) {
        uint32_t phm = 0u;
        for (int s = 0; s < S; s++) {
            const int buf = s % NBUF;
            if (s >= NBUF) {
                mbar_wait(sb + OFF_MMA + 8 * buf, (phm >> buf) & 1u);
                phm ^= 1u << buf;
            }
            const uint32_t st   = sb + SMEM_STAGE0 + buf * T2_BYTES;
            const uint32_t fbar = sb + OFF_FULL + 8 * buf;
            if (leader) mbar_expect(fbar, 2 * T2_BYTES);
            const int k0 = s * 32;
            tma2d_cg2(st + T2_A0HI, &mapAhi, k0, aRow0, fbar);
            tma2d_cg2(st + T2_A0LO, &mapAlo, k0, aRow0, fbar);
            tma2d_cg2(st + T2_A1HI, &mapAhi, k0, aRow1, fbar);
            tma2d_cg2(st + T2_A1LO, &mapAlo, k0, aRow1, fbar);
            tma2d_cg2(st + T2_BHI,  &mapBhi, k0, bRow,  fbar);
            tma2d_cg2(st + T2_BLO,  &mapBlo, k0, bRow,  fbar);
        }
        for (int t = (S >= NBUF ? S - NBUF : 0); t < S; t++) {
            const int buf = t % NBUF;
            mbar_wait(sb + OFF_MMA + 8 * buf, (phm >> buf) & 1u);
            phm ^= 1u << buf;
        }
    } else if (wid == 0 && leader) {
        uint32_t phf = 0u;
        for (int s = 0; s < S; s++) {
            const int buf = s % NBUF;
            mbar_wait(sb + OFF_FULL + 8 * buf, (phf >> buf) & 1u);
            phf ^= 1u << buf;
            if (elect_one()) {
                const uint32_t st = sb + SMEM_STAGE0 + buf * T2_BYTES;
                uint64_t da0h = make_desc64(st + T2_A0HI);
                uint64_t da0l = make_desc64(st + T2_A0LO);
                uint64_t da1h = make_desc64(st + T2_A1HI);
                uint64_t da1l = make_desc64(st + T2_A1LO);
                uint64_t dbh  = make_desc64(st + T2_BHI);
                uint64_t dbl  = make_desc64(st + T2_BLO);
                #pragma unroll
                for (int k = 0; k < 2; k++) {
                    bool en0 = !(s == 0 && k == 0);
                    mma_ss_cg2(tmem,       da0h + 2*k, dbh + 2*k, IDESC_BF16_M256_N256, en0);
                    mma_ss_cg2(tmem,       da0h + 2*k, dbl + 2*k, IDESC_BF16_M256_N256, true);
                    mma_ss_cg2(tmem,       da0l + 2*k, dbh + 2*k, IDESC_BF16_M256_N256, true);
                    mma_ss_cg2(tmem + 256, da1h + 2*k, dbh + 2*k, IDESC_BF16_M256_N256, en0);
                    mma_ss_cg2(tmem + 256, da1h + 2*k, dbl + 2*k, IDESC_BF16_M256_N256, true);
                    mma_ss_cg2(tmem + 256, da1l + 2*k, dbh + 2*k, IDESC_BF16_M256_N256, true);
                }
                TCG_COMMIT_CG2_MC(sb + OFF_MMA + 8 * buf, 0x3);
            }
        }
    }

    __syncthreads();
    TCG_FENCE_AFTER();

    // pad mask
    float* mS = (float*)(smem + OFF_MASK);
    for (int i = tid; i < 256; i += 128)
        mS[i] = (Eg[((size_t)b * N + nB + i) * HDIM] == 0.0f) ? 1.0f : 0.0f;
    __syncthreads();

    #pragma unroll
    for (int t = 0; t < 2; t++) {
        const int row = mB + t * 256 + (int)rank * 128 + wid * 32 + lid;
        float* crow = Cg + ((size_t)b * M + row) * N + nB;
        for (int cc = 0; cc < 8; cc++) {
            uint32_t r[32];
            TCG_LD_X32(r, tmem + t * 256 + cc * 32);
            TCG_WAIT_LD();
            #pragma unroll
            for (int j = 0; j < 32; j += 4) {
                float4 v;
                v.x = __uint_as_float(r[j + 0]);
                v.y = __uint_as_float(r[j + 1]);
                v.z = __uint_as_float(r[j + 2]);
                v.w = __uint_as_float(r[j + 3]);
                if (mS[cc * 32 + j + 0] != 0.0f) v.x = -CUDART_INF_F;
                if (mS[cc * 32 + j + 1] != 0.0f) v.y = -CUDART_INF_F;
                if (mS[cc * 32 + j + 2] != 0.0f) v.z = -CUDART_INF_F;
                if (mS[cc * 32 + j + 3] != 0.0f) v.w = -CUDART_INF_F;
                *reinterpret_cast<float4*>(crow + cc * 32 + j) = v;
            }
        }
    }

    __syncthreads();
    if (wid == 0) {
        TCG_RELINQ_CG2();
        TCG_DEALLOC_CG2(tmem, 512);
    }
    CLUSTER_SYNC_ALL();
#endif // TC_OK
}

// ---------------------------------------------------------------------------
// CONTEXT: cg2 pair tile 256x256, K=64 (SW128), NBUF=3 (R13 engine).
//   grid: x = M/128 (per-CTA rows; pair via cluster x), y = N/256, z = batch
// ---------------------------------------------------------------------------
__global__ __launch_bounds__(128, 1) __cluster_dims__(2, 1, 1)
void context_cg2(const __grid_constant__ CUtensorMap mapAhi,
                 const __grid_constant__ CUtensorMap mapAlo,
                 const __grid_constant__ CUtensorMap mapBhi,
                 const __grid_constant__ CUtensorMap mapBlo,
                 float* __restrict__ Cg, int M, int N, int K)
{
#if TC_OK
    extern __shared__ char smem[];
    const uint32_t sb = smem_u32(smem);
    const int tid = threadIdx.x;
    const int wid = tid >> 5, lid = tid & 31;
    const int b   = blockIdx.z;
    const int mB  = blockIdx.x * 128;
    const int nB  = blockIdx.y * 256;
    uint32_t rank;
    asm("mov.u32 %0, %%cluster_ctarank;" : "=r"(rank));
    const bool leader = (rank == 0);

    const int S = K / 64;

    if (wid == 0) TCG_ALLOC_CG2(sb + OFF_TMEMPTR, 256);
    if (tid == 0) {
        #pragma unroll
        for (int i = 0; i < NBUF; i++) {
            mbar_init(sb + OFF_FULL + 8 * i, 1);
            mbar_init(sb + OFF_MMA  + 8 * i, 1);
        }
    }
    __syncthreads();
    uint32_t tmem;
    asm volatile("ld.shared.b32 %0, [%1];" : "=r"(tmem) : "r"(sb + OFF_TMEMPTR));

    CLUSTER_SYNC_ALL();

    const int aRow = b * M + mB;
    const int bRow = b * N + nB + (int)rank * 128;

    if (wid == 1 && lid == 0) {
        uint32_t phm = 0u;
        for (int s = 0; s < S; s++) {
            const int buf = s % NBUF;
            if (s >= NBUF) {
                mbar_wait(sb + OFF_MMA + 8 * buf, (phm >> buf) & 1u);
                phm ^= 1u << buf;
            }
            const uint32_t st   = sb + SMEM_STAGE0 + buf * CG_BYTES;
            const uint32_t fbar = sb + OFF_FULL + 8 * buf;
            if (leader) mbar_expect(fbar, 2 * CG_BYTES);
            const int k0 = s * 64;
            tma2d_cg2(st + CG_AHI, &mapAhi, k0, aRow, fbar);
            tma2d_cg2(st + CG_ALO, &mapAlo, k0, aRow, fbar);
            tma2d_cg2(st + CG_BHI, &mapBhi, k0, bRow, fbar);
            tma2d_cg2(st + CG_BLO, &mapBlo, k0, bRow, fbar);
        }
        for (int t = (S >= NBUF ? S - NBUF : 0); t < S; t++) {
            const int buf = t % NBUF;
            mbar_wait(sb + OFF_MMA + 8 * buf, (phm >> buf) & 1u);
            phm ^= 1u << buf;
        }
    } else if (wid == 0 && leader) {
        uint32_t phf = 0u;
        for (int s = 0; s < S; s++) {
            const int buf = s % NBUF;
            mbar_wait(sb + OFF_FULL + 8 * buf, (phf >> buf) & 1u);
            phf ^= 1u << buf;
            if (elect_one()) {
                const uint32_t st = sb + SMEM_STAGE0 + buf * CG_BYTES;
                uint64_t dah = make_desc128(st + CG_AHI);
                uint64_t dal = make_desc128(st + CG_ALO);
                uint64_t dbh = make_desc128(st + CG_BHI);
                uint64_t dbl = make_desc128(st + CG_BLO);
                #pragma unroll
                for (int k = 0; k < 4; k++) {
                    bool en0 = !(s == 0 && k == 0);
                    mma_ss_cg2(tmem, dah + 2 * k, dbh + 2 * k, IDESC_BF16_M256_N256, en0);
                    mma_ss_cg2(tmem, dah + 2 * k, dbl + 2 * k, IDESC_BF16_M256_N256, true);
                    mma_ss_cg2(tmem, dal + 2 * k, dbh + 2 * k, IDESC_BF16_M256_N256, true);
                }
                TCG_COMMIT_CG2_MC(sb + OFF_MMA + 8 * buf, 0x3);
            }
        }
    }

    __syncthreads();
    TCG_FENCE_AFTER();

    const int row = mB + wid * 32 + lid;
    float* crow = Cg + ((size_t)b * M + row) * N + nB;
    for (int cc = 0; cc < 8; cc++) {
        uint32_t r[32];
        TCG_LD_X32(r, tmem + cc * 32);
        TCG_WAIT_LD();
        #pragma unroll
        for (int j = 0; j < 32; j += 4) {
            float4 v;
            v.x = __uint_as_float(r[j + 0]);
            v.y = __uint_as_float(r[j + 1]);
            v.z = __uint_as_float(r[j + 2]);
            v.w = __uint_as_float(r[j + 3]);
            *reinterpret_cast<float4*>(crow + cc * 32 + j) = v;
        }
    }

    __syncthreads();
    if (wid == 0) {
        TCG_RELINQ_CG2();
        TCG_DEALLOC_CG2(tmem, 256);
    }
    CLUSTER_SYNC_ALL();
#endif // TC_OK
}

// ---------------------------------------------------------------------------
// FALLBACK: cp.async cg1 GEMM (used only if tensormap encode is unavailable)
// ---------------------------------------------------------------------------
__device__ __forceinline__ void load_tile(uint32_t sdst, const bf16* g,
                                          int rows, int ldk, int tid)
{
    for (int idx = tid; idx < rows * 8; idx += 128) {
        int r = idx >> 3, seg = idx & 7;
        uint32_t bo = (uint32_t)(r * 128 + seg * 16);
        cpasync16(sdst + SWZ128(bo), g + (size_t)r * ldk + seg * 8);
    }
}

template<bool MASK>
__global__ __launch_bounds__(128)
void mma_gemm_fb(const bf16* __restrict__ Ahi, const bf16* __restrict__ Alo,
                 const bf16* __restrict__ Bhi, const bf16* __restrict__ Blo,
                 const float* __restrict__ Eg, float* __restrict__ Cg,
                 int M, int N, int K)
{
#if TC_OK
    extern __shared__ char smem[];
    const uint32_t sb  = smem_u32(smem);
    const int tid = threadIdx.x;
    const int wid = tid >> 5, lid = tid & 31;
    const int b   = blockIdx.z;
    const int mB  = blockIdx.y * 128;
    const int nB  = blockIdx.x * 256;

    const bf16* aH = Ahi + ((size_t)b * M + mB) * K;
    const bf16* aL = Alo + ((size_t)b * M + mB) * K;
    const bf16* bH = Bhi + ((size_t)b * N + nB) * K;
    const bf16* bL = Blo + ((size_t)b * N + nB) * K;

    if (wid == 0) TCG_ALLOC(sb + OFF_TMEMPTR, 256);
    if (tid == 0) {
        mbar_init(sb + OFF_MMA, 1);
        mbar_init(sb + OFF_MMA + 8, 1);
    }
    __syncthreads();
    uint32_t tmem;
    asm volatile("ld.shared.b32 %0, [%1];" : "=r"(tmem) : "r"(sb + OFF_TMEMPTR));

    const int S = K / 64;
    {
        uint32_t st = sb + SMEM_STAGE0;
        load_tile(st + OFF_AHI, aH, 128, K, tid);
        load_tile(st + OFF_ALO, aL, 128, K, tid);
        load_tile(st + OFF_BHI, bH, 256, K, tid);
        load_tile(st + OFF_BLO, bL, 256, K, tid);
        asm volatile("cp.async.commit_group;" ::: "memory");
    }
    uint32_t ph[2] = {0u, 0u};
    for (int s = 0; s < S; s++) {
        const int buf  = s & 1;
        const int nbuf = buf ^ 1;
        if (s + 1 < S) {
            if (s >= 1) {
                mbar_wait(sb + OFF_MMA + 8 * nbuf, ph[nbuf]);
                ph[nbuf] ^= 1;
            }
            const int k0 = (s + 1) * 64;
            uint32_t st = sb + SMEM_STAGE0 + nbuf * STAGE_BYTES;
            load_tile(st + OFF_AHI, aH + k0, 128, K, tid);
            load_tile(st + OFF_ALO, aL + k0, 128, K, tid);
            load_tile(st + OFF_BHI, bH + k0, 256, K, tid);
            load_tile(st + OFF_BLO, bL + k0, 256, K, tid);
            asm volatile("cp.async.commit_group;" ::: "memory");
            asm volatile("cp.async.wait_group 1;" ::: "memory");
        } else {
            asm volatile("cp.async.wait_group 0;" ::: "memory");
        }
        __syncthreads();
        if (wid == 0) {
            asm volatile("fence.proxy.async.shared::cta;" ::: "memory");
            if (elect_one()) {
                uint32_t st = sb + SMEM_STAGE0 + buf * STAGE_BYTES;
                uint64_t dah = make_desc128(st + OFF_AHI);
                uint64_t dal = make_desc128(st + OFF_ALO);
                uint64_t dbh = make_desc128(st + OFF_BHI);
                uint64_t dbl = make_desc128(st + OFF_BLO);
                #pragma unroll
                for (int k = 0; k < 4; k++) {
                    bool en0 = !(s == 0 && k == 0);
                    mma_ss(tmem, dah + 2 * k, dbh + 2 * k, IDESC_BF16_M128_N256, en0);
                    mma_ss(tmem, dah + 2 * k, dbl + 2 * k, IDESC_BF16_M128_N256, true);
                    mma_ss(tmem, dal + 2 * k, dbh + 2 * k, IDESC_BF16_M128_N256, true);
                }
                TCG_COMMIT(sb + OFF_MMA + 8 * buf);
            }
        }
    }
    const int lb = (S - 1) & 1;
    mbar_wait(sb + OFF_MMA + 8 * lb, ph[lb]);
    TCG_FENCE_AFTER();

    float* mS = (float*)(smem + OFF_MASK);
    if (MASK) {
        for (int i = tid; i < 256; i += 128)
            mS[i] = (Eg[((size_t)b * N + nB + i) * HDIM] == 0.0f) ? 1.0f : 0.0f;
    }
    __syncthreads();

    const int row = mB + wid * 32 + lid;
    float* crow = Cg + ((size_t)b * M + row) * N + nB;
    for (int cc = 0; cc < 8; cc++) {
        uint32_t r[32];
        TCG_LD_X32(r, tmem + cc * 32);
        TCG_WAIT_LD();
        #pragma unroll
        for (int j = 0; j < 32; j += 4) {
            float4 v;
            v.x = __uint_as_float(r[j + 0]);
            v.y = __uint_as_float(r[j + 1]);
            v.z = __uint_as_float(r[j + 2]);
            v.w = __uint_as_float(r[j + 3]);
            if (MASK) {
                if (mS[cc * 32 + j + 0] != 0.0f) v.x = -CUDART_INF_F;
                if (mS[cc * 32 + j + 1] != 0.0f) v.y = -CUDART_INF_F;
                if (mS[cc * 32 + j + 2] != 0.0f) v.z = -CUDART_INF_F;
                if (mS[cc * 32 + j + 3] != 0.0f) v.w = -CUDART_INF_F;
            }
            *reinterpret_cast<float4*>(crow + cc * 32 + j) = v;
        }
    }
    __syncthreads();
    if (wid == 0) {
        TCG_RELINQ();
        TCG_DEALLOC(tmem, 256);
    }
#endif // TC_OK
}

// ---------------------------------------------------------------------------
// Row softmax (2048), in place, also emits P hi/lo bf16.
// ---------------------------------------------------------------------------
__inline__ __device__ float warpMax(float v) {
    #pragma unroll
    for (int o = 16; o > 0; o >>= 1) v = fmaxf(v, __shfl_xor_sync(0xffffffffu, v, o));
    return v;
}
__inline__ __device__ float warpSum(float v) {
    #pragma unroll
    for (int o = 16; o > 0; o >>= 1) v += __shfl_xor_sync(0xffffffffu, v, o);
    return v;
}

__global__ __launch_bounds__(256)
void softmax_split_kernel(float* __restrict__ attn,
                          bf16* __restrict__ Phi, bf16* __restrict__ Plo)
{
    const size_t row = blockIdx.x;
    float* p = attn + row * (size_t)ENC;
    const int tid = threadIdx.x;

    float4 v0 = reinterpret_cast<float4*>(p)[tid];
    float4 v1 = reinterpret_cast<float4*>(p)[tid + 256];

    __shared__ float smax[8];
    __shared__ float ssum[8];

    float m = fmaxf(fmaxf(fmaxf(v0.x, v0.y), fmaxf(v0.z, v0.w)),
                    fmaxf(fmaxf(v1.x, v1.y), fmaxf(v1.z, v1.w)));
    float wm = warpMax(m);
    if ((tid & 31) == 0) smax[tid >> 5] = wm;
    __syncthreads();
    if (tid < 32) {
        float t = (tid < 8) ? smax[tid] : -CUDART_INF_F;
        t = warpMax(t);
        if (tid == 0) smax[0] = t;
    }
    __syncthreads();
    const float bm = smax[0];

    v0.x = __expf(v0.x - bm); v0.y = __expf(v0.y - bm);
    v0.z = __expf(v0.z - bm); v0.w = __expf(v0.w - bm);
    v1.x = __expf(v1.x - bm); v1.y = __expf(v1.y - bm);
    v1.z = __expf(v1.z - bm); v1.w = __expf(v1.w - bm);

    float s = (v0.x + v0.y + v0.z + v0.w) + (v1.x + v1.y + v1.z + v1.w);
    float ws = warpSum(s);
    if ((tid & 31) == 0) ssum[tid >> 5] = ws;
    __syncthreads();
    if (tid < 32) {
        float t = (tid < 8) ? ssum[tid] : 0.0f;
        t = warpSum(t);
        if (tid == 0) ssum[0] = t;
    }
    __syncthreads();
    const float inv = 1.0f / ssum[0];

    v0.x *= inv; v0.y *= inv; v0.z *= inv; v0.w *= inv;
    v1.x *= inv; v1.y *= inv; v1.z *= inv; v1.w *= inv;

    reinterpret_cast<float4*>(p)[tid]       = v0;
    reinterpret_cast<float4*>(p)[tid + 256] = v1;

    uint2 h0, l0, h1, l1;
    pack4(v0, h0, l0);
    pack4(v1, h1, l1);
    uint2* ph = reinterpret_cast<uint2*>(Phi + row * (size_t)ENC);
    uint2* pl = reinterpret_cast<uint2*>(Plo + row * (size_t)ENC);
    ph[tid]       = h0;  ph[tid + 256] = h1;
    pl[tid]       = l0;  pl[tid + 256] = l1;
}

// ---------------------------------------------------------------------------
// Host
// ---------------------------------------------------------------------------
typedef CUresult (*EncodeFn)(
    CUtensorMap*, CUtensorMapDataType, cuuint32_t, void*,
    const cuuint64_t*, const cuuint64_t*, const cuuint32_t*, const cuuint32_t*,
    CUtensorMapInterleave, CUtensorMapSwizzle, CUtensorMapL2promotion,
    CUtensorMapFloatOOBfill);

static bool encode_sw64(EncodeFn fn, CUtensorMap* m, void* base,
                        uint64_t kdim, uint64_t rows)
{
    cuuint64_t dims[2]    = {kdim, rows};
    cuuint64_t strides[1] = {kdim * 2};
    cuuint32_t box[2]     = {32u, 128u};          // 32 bf16 = 64B (SW64), 128 rows
    cuuint32_t estr[2]    = {1u, 1u};
    CUresult r = fn(m, CU_TENSOR_MAP_DATA_TYPE_BFLOAT16, 2, base,
                    dims, strides, box, estr,
                    CU_TENSOR_MAP_INTERLEAVE_NONE, CU_TENSOR_MAP_SWIZZLE_64B,
                    CU_TENSOR_MAP_L2_PROMOTION_L2_128B,
                    CU_TENSOR_MAP_FLOAT_OOB_FILL_NONE);
    return r == CUDA_SUCCESS;
}

static bool encode_sw128(EncodeFn fn, CUtensorMap* m, void* base,
                         uint64_t kdim, uint64_t rows)
{
    cuuint64_t dims[2]    = {kdim, rows};
    cuuint64_t strides[1] = {kdim * 2};
    cuuint32_t box[2]     = {64u, 128u};          // 64 bf16 = 128B (SW128)
    cuuint32_t estr[2]    = {1u, 1u};
    CUresult r = fn(m, CU_TENSOR_MAP_DATA_TYPE_BFLOAT16, 2, base,
                    dims, strides, box, estr,
                    CU_TENSOR_MAP_INTERLEAVE_NONE, CU_TENSOR_MAP_SWIZZLE_128B,
                    CU_TENSOR_MAP_L2_PROMOTION_L2_128B,
                    CU_TENSOR_MAP_FLOAT_OOB_FILL_NONE);
    return r == CUDA_SUCCESS;
}

extern "C" void kernel_launch(void* const* d_in, const int* in_sizes, int n_in,
                              void* d_out, int out_size)
{
    const float* D = (const float*)d_in[0];
    const float* E = (const float*)d_in[1];

    float* ctx  = (float*)d_out;                        // [16,2048,1024]
    float* attn = ctx + (size_t)BATCH * DEC * HDIM;     // [16,2048,2048]

    void *pDhi, *pDlo, *pEhi, *pElo, *pEThi, *pETlo, *pPhi, *pPlo;
    cudaGetSymbolAddress(&pDhi,  g_Dhi);
    cudaGetSymbolAddress(&pDlo,  g_Dlo);
    cudaGetSymbolAddress(&pEhi,  g_Ehi);
    cudaGetSymbolAddress(&pElo,  g_Elo);
    cudaGetSymbolAddress(&pEThi, g_EThi);
    cudaGetSymbolAddress(&pETlo, g_ETlo);
    cudaGetSymbolAddress(&pPhi,  g_Phi);
    cudaGetSymbolAddress(&pPlo,  g_Plo);

    cudaFuncSetAttribute(scores_t2,
                         cudaFuncAttributeMaxDynamicSharedMemorySize, T2_SMEM);
    cudaFuncSetAttribute(context_cg2,
                         cudaFuncAttributeMaxDynamicSharedMemorySize, CG_SMEM);
    cudaFuncSetAttribute(mma_gemm_fb<true>,
                         cudaFuncAttributeMaxDynamicSharedMemorySize, FB_SMEM);
    cudaFuncSetAttribute(mma_gemm_fb<false>,
                         cudaFuncAttributeMaxDynamicSharedMemorySize, FB_SMEM);

    EncodeFn enc = nullptr;
    {
        void* fp = nullptr;
        cudaDriverEntryPointQueryResult qr = cudaDriverEntryPointSymbolNotFound;
        if (cudaGetDriverEntryPoint("cuTensorMapEncodeTiled", &fp,
                                    cudaEnableDefault, &qr) == cudaSuccess &&
            qr == cudaDriverEntryPointSuccess)
            enc = (EncodeFn)fp;
    }

    // scores maps (SW64, 128-row boxes); context maps (SW128, 128-row boxes)
    CUtensorMap mDhi, mDlo, mEhi, mElo, mPhi, mPlo, mEThi, mETlo;
    bool tma_ok = (enc != nullptr);
    if (tma_ok) {
        tma_ok =
            encode_sw64 (enc, &mDhi,  pDhi,  HDIM, (uint64_t)BATCH * DEC)  &&
            encode_sw64 (enc, &mDlo,  pDlo,  HDIM, (uint64_t)BATCH * DEC)  &&
            encode_sw64 (enc, &mEhi,  pEhi,  HDIM, (uint64_t)BATCH * ENC)  &&
            encode_sw64 (enc, &mElo,  pElo,  HDIM, (uint64_t)BATCH * ENC)  &&
            encode_sw128(enc, &mPhi,  pPhi,  ENC,  (uint64_t)BATCH * DEC)  &&
            encode_sw128(enc, &mPlo,  pPlo,  ENC,  (uint64_t)BATCH * DEC)  &&
            encode_sw128(enc, &mEThi, pEThi, ENC,  (uint64_t)BATCH * HDIM) &&
            encode_sw128(enc, &mETlo, pETlo, ENC,  (uint64_t)BATCH * HDIM);
    }

    const int n4 = BATCH * DEC * HDIM / 4;
    split_kernel<<<n4 / 256, 256>>>((const float4*)D, (uint2*)pDhi, (uint2*)pDlo, n4);
    split_kernel<<<n4 / 256, 256>>>((const float4*)E, (uint2*)pEhi, (uint2*)pElo, n4);

    transpose_split_kernel<<<dim3(ENC / 32, HDIM / 32, BATCH), dim3(32, 8)>>>(
        E, (bf16*)pEThi, (bf16*)pETlo);

    if (tma_ok) {
        // scores: T2 engine — grid x = M/256 (pairs of CTAs), y = N/256
        scores_t2<<<dim3(DEC / 256, ENC / 256, BATCH), 128, T2_SMEM>>>(
            mDhi, mDlo, mEhi, mElo, E, attn, DEC, ENC, HDIM);
    } else {
        mma_gemm_fb<true><<<dim3(ENC / 256, DEC / 128, BATCH), 128, FB_SMEM>>>(
            (const bf16*)pDhi, (const bf16*)pDlo,
            (const bf16*)pEhi, (const bf16*)pElo, E, attn, DEC, ENC, HDIM);
    }

    softmax_split_kernel<<<BATCH * DEC, 256>>>(attn, (bf16*)pPhi, (bf16*)pPlo);

    if (tma_ok) {
        // context: cg2-K64 engine — grid x = M/128 (pairs via cluster), y = N/256
        context_cg2<<<dim3(DEC / 128, HDIM / 256, BATCH), 128, CG_SMEM>>>(
            mPhi, mPlo, mEThi, mETlo, ctx, DEC, HDIM, ENC);
    } else {
        mma_gemm_fb<false><<<dim3(HDIM / 256, DEC / 128, BATCH), 128, FB_SMEM>>>(
            (const bf16*)pPhi, (const bf16*)pPlo,
            (const bf16*)pEThi, (const bf16*)pETlo, nullptr, ctx, DEC, HDIM, ENC);
    }
}

// round 17
// speedup vs baseline: 1.0266x; 1.0011x over previous
#include <cuda_runtime.h>
#include <cuda.h>
#include <cuda_bf16.h>
#include <math_constants.h>
#include <cstdint>

#define BATCH 16
#define DEC   2048
#define ENC   2048
#define HDIM  1024

#if defined(__CUDA_ARCH_SPECIFIC__) || defined(__CUDA_ARCH_FEAT_SM103_ALL) || defined(__CUDA_ARCH_FEAT_SM100_ALL)
#define TC_OK 1
#else
#define TC_OK 0
#endif

typedef __nv_bfloat16 bf16;

// ---------------------------------------------------------------------------
// Scratch (static device globals)
// ---------------------------------------------------------------------------
__device__ bf16 g_Dhi [(size_t)BATCH * DEC  * HDIM];
__device__ bf16 g_Dlo [(size_t)BATCH * DEC  * HDIM];
__device__ bf16 g_Ehi [(size_t)BATCH * ENC  * HDIM];
__device__ bf16 g_Elo [(size_t)BATCH * ENC  * HDIM];
__device__ bf16 g_EThi[(size_t)BATCH * HDIM * ENC ];
__device__ bf16 g_ETlo[(size_t)BATCH * HDIM * ENC ];
__device__ bf16 g_Phi [(size_t)BATCH * DEC  * ENC ];
__device__ bf16 g_Plo [(size_t)BATCH * DEC  * ENC ];

// ---------------------------------------------------------------------------
// PTX helpers
// ---------------------------------------------------------------------------
__device__ __forceinline__ uint32_t smem_u32(const void* p) {
    uint32_t a;
    asm("{ .reg .u64 t; cvta.to.shared.u64 t, %1; cvt.u32.u64 %0, t; }"
        : "=r"(a) : "l"(p));
    return a;
}

__device__ __forceinline__ bool elect_one() {
    uint32_t p;
    asm volatile("{\n .reg .pred p;\n elect.sync _|p, 0xFFFFFFFF;\n"
                 " selp.b32 %0, 1, 0, p;\n}" : "=r"(p));
    return p != 0;
}

#define SWZ128(b) ((b) ^ (((b) >> 3) & 0x70))

__device__ __forceinline__ void cpasync16(uint32_t s, const void* g) {
    asm volatile("cp.async.cg.shared.global [%0], [%1], 16;"
                 :: "r"(s), "l"(g) : "memory");
}

__device__ __forceinline__ void mbar_init(uint32_t m, uint32_t cnt) {
    asm volatile("mbarrier.init.shared.b64 [%0], %1;" :: "r"(m), "r"(cnt) : "memory");
}

__device__ __forceinline__ void mbar_expect(uint32_t m, uint32_t tx) {
    asm volatile("mbarrier.arrive.expect_tx.shared.b64 _, [%0], %1;"
                 :: "r"(m), "r"(tx) : "memory");
}

__device__ __forceinline__ void mbar_wait(uint32_t m, uint32_t phase) {
    asm volatile(
        "{\n .reg .pred P;\n"
        "LAB%=:\n"
        " mbarrier.try_wait.parity.acquire.cta.shared::cta.b64 P, [%0], %1, 0x989680;\n"
        " @P bra DONE%=;\n"
        " bra LAB%=;\n"
        "DONE%=:\n}"
        :: "r"(m), "r"(phase) : "memory");
}

#define CLUSTER_SYNC_ALL() do { \
    asm volatile("barrier.cluster.arrive.aligned;" ::: "memory"); \
    asm volatile("barrier.cluster.wait.aligned;"   ::: "memory"); \
} while (0)

// SW128 K-major SMEM descriptor (Blackwell, version=1)
static constexpr uint64_t DESC_BASE_SW128 =
    (2ull << 61) | (1ull << 46) | (64ull << 32) | (1ull << 16);
__device__ __forceinline__ uint64_t make_desc128(uint32_t addr) {
    return DESC_BASE_SW128 | ((uint64_t)(addr >> 4) & 0x3FFF);
}

#if TC_OK
// cg1 MMA (fallback)
__device__ __forceinline__ void mma_ss(uint32_t d, uint64_t a, uint64_t b,
                                       uint32_t idesc, bool en) {
    uint32_t e = en ? 1u : 0u;
    asm volatile(
        "{\n .reg .pred p;\n setp.ne.u32 p, %4, 0;\n"
        " tcgen05.mma.cta_group::1.kind::f16 [%0], %1, %2, %3, {%5,%5,%5,%5}, p;\n}"
        :: "r"(d), "l"(a), "l"(b), "r"(idesc), "r"(e), "r"(0u) : "memory");
}

// cg2 MMA: M=256 across the CTA pair, SS mode
__device__ __forceinline__ void mma_ss_cg2(uint32_t d, uint64_t a, uint64_t b,
                                           uint32_t idesc, bool en) {
    uint32_t e = en ? 1u : 0u;
    asm volatile(
        "{\n .reg .pred p;\n setp.ne.u32 p, %4, 0;\n"
        " tcgen05.mma.cta_group::2.kind::f16 [%0], %1, %2, %3, "
        "{%5,%5,%5,%5,%5,%5,%5,%5}, p;\n}"
        :: "r"(d), "l"(a), "l"(b), "r"(idesc), "r"(e), "r"(0u) : "memory");
}

// cg2 TMA 2D load: both CTAs execute; complete_tx targets the LEADER's barrier
__device__ __forceinline__ void tma2d_cg2(uint32_t dst, const CUtensorMap* map,
                                          int x, int y, uint32_t bar) {
    asm volatile(
        "{\n .reg .b32 lb;\n and.b32 lb, %4, 0xFEFFFFFF;\n"
        " cp.async.bulk.tensor.2d.cta_group::2.shared::cluster.global.tile"
        ".mbarrier::complete_tx::bytes [%0], [%1, {%2, %3}], [lb];\n}"
        :: "r"(dst), "l"(map), "r"(x), "r"(y), "r"(bar) : "memory");
}

#define TCG_ALLOC(sm, n) \
    asm volatile("tcgen05.alloc.cta_group::1.sync.aligned.shared::cta.b32 [%0], %1;" \
                 :: "r"(sm), "r"(n) : "memory")
#define TCG_DEALLOC(t, n) \
    asm volatile("tcgen05.dealloc.cta_group::1.sync.aligned.b32 %0, %1;" :: "r"(t), "r"(n))
#define TCG_RELINQ() \
    asm volatile("tcgen05.relinquish_alloc_permit.cta_group::1.sync.aligned;")
#define TCG_COMMIT(m) \
    asm volatile("tcgen05.commit.cta_group::1.mbarrier::arrive::one.shared::cluster.b64 [%0];" \
                 :: "r"(m) : "memory")

#define TCG_ALLOC_CG2(sm, n) \
    asm volatile("tcgen05.alloc.cta_group::2.sync.aligned.shared::cta.b32 [%0], %1;" \
                 :: "r"(sm), "r"(n) : "memory")
#define TCG_DEALLOC_CG2(t, n) \
    asm volatile("tcgen05.dealloc.cta_group::2.sync.aligned.b32 %0, %1;" :: "r"(t), "r"(n))
#define TCG_RELINQ_CG2() \
    asm volatile("tcgen05.relinquish_alloc_permit.cta_group::2.sync.aligned;")
#define TCG_COMMIT_CG2_MC(m, mask) \
    asm volatile("tcgen05.commit.cta_group::2.mbarrier::arrive::one.shared::cluster" \
                 ".multicast::cluster.b64 [%0], %1;" \
                 :: "r"(m), "h"((uint16_t)(mask)) : "memory")

#define TCG_FENCE_AFTER()  asm volatile("tcgen05.fence::after_thread_sync;" ::: "memory")
#define TCG_WAIT_LD()      asm volatile("tcgen05.wait::ld.sync.aligned;" ::: "memory")

#define TCG_LD_X32(r, ta) \
    asm volatile( \
        "tcgen05.ld.sync.aligned.32x32b.x32.b32 " \
        "{%0, %1, %2, %3, %4, %5, %6, %7, " \
        " %8, %9, %10, %11, %12, %13, %14, %15, " \
        " %16, %17, %18, %19, %20, %21, %22, %23, " \
        " %24, %25, %26, %27, %28, %29, %30, %31}, [%32];" \
        : "=r"((r)[0]),  "=r"((r)[1]),  "=r"((r)[2]),  "=r"((r)[3]), \
          "=r"((r)[4]),  "=r"((r)[5]),  "=r"((r)[6]),  "=r"((r)[7]), \
          "=r"((r)[8]),  "=r"((r)[9]),  "=r"((r)[10]), "=r"((r)[11]), \
          "=r"((r)[12]), "=r"((r)[13]), "=r"((r)[14]), "=r"((r)[15]), \
          "=r"((r)[16]), "=r"((r)[17]), "=r"((r)[18]), "=r"((r)[19]), \
          "=r"((r)[20]), "=r"((r)[21]), "=r"((r)[22]), "=r"((r)[23]), \
          "=r"((r)[24]), "=r"((r)[25]), "=r"((r)[26]), "=r"((r)[27]), \
          "=r"((r)[28]), "=r"((r)[29]), "=r"((r)[30]), "=r"((r)[31]) \
        : "r"(ta))
#endif // TC_OK

// ---------------------------------------------------------------------------
// fp32 -> bf16 hi/lo split helpers
// ---------------------------------------------------------------------------
__device__ __forceinline__ void split1(float x, bf16& h, bf16& l) {
    h = __float2bfloat16(x);
    l = __float2bfloat16(x - __bfloat162float(h));
}
__device__ __forceinline__ void pack4(float4 v, uint2& h, uint2& l) {
    bf16 h0, l0, h1, l1, h2, l2, h3, l3;
    split1(v.x, h0, l0); split1(v.y, h1, l1);
    split1(v.z, h2, l2); split1(v.w, h3, l3);
    h.x = ((uint32_t)__bfloat16_as_ushort(h1) << 16) | __bfloat16_as_ushort(h0);
    h.y = ((uint32_t)__bfloat16_as_ushort(h3) << 16) | __bfloat16_as_ushort(h2);
    l.x = ((uint32_t)__bfloat16_as_ushort(l1) << 16) | __bfloat16_as_ushort(l0);
    l.y = ((uint32_t)__bfloat16_as_ushort(l3) << 16) | __bfloat16_as_ushort(l2);
}

__global__ __launch_bounds__(256)
void split_kernel(const float4* __restrict__ in, uint2* __restrict__ hi,
                  uint2* __restrict__ lo, int n4)
{
    int i = blockIdx.x * 256 + threadIdx.x;
    if (i >= n4) return;
    float4 v = in[i];
    uint2 h, l;
    pack4(v, h, l);
    hi[i] = h;
    lo[i] = l;
}

// Fused: read E once; write row-major Ehi/Elo AND transposed EThi/ETlo.
__global__ __launch_bounds__(256)
void fused_split_transpose_kernel(const float* __restrict__ E,
                                  bf16* __restrict__ Eh, bf16* __restrict__ El,
                                  bf16* __restrict__ Th, bf16* __restrict__ Tl)
{
    __shared__ float t[32][33];
    const int b  = blockIdx.z;
    const int e0 = blockIdx.x << 5;
    const int h0 = blockIdx.y << 5;
    const int tx = threadIdx.x, ty = threadIdx.y;   // 32 x 8

    const float* src = E + (size_t)b * ENC * HDIM;
    bf16* eh = Eh + (size_t)b * ENC * HDIM;
    bf16* el = El + (size_t)b * ENC * HDIM;
    #pragma unroll
    for (int r = 0; r < 32; r += 8) {
        size_t o = (size_t)(e0 + ty + r) * HDIM + h0 + tx;
        float x = src[o];
        t[ty + r][tx] = x;
        bf16 h, l; split1(x, h, l);
        eh[o] = h;
        el[o] = l;
    }
    __syncthreads();

    bf16* th = Th + (size_t)b * HDIM * ENC;
    bf16* tl = Tl + (size_t)b * HDIM * ENC;
    #pragma unroll
    for (int r = 0; r < 32; r += 8) {
        float x = t[tx][ty + r];
        bf16 h, l; split1(x, h, l);
        size_t o = (size_t)(h0 + ty + r) * ENC + e0 + tx;
        th[o] = h;
        tl[o] = l;
    }
}

// ---------------------------------------------------------------------------
// Shared GEMM constants
// ---------------------------------------------------------------------------
static constexpr uint32_t IDESC_BF16_M128_N256 =
    (1u << 4) | (1u << 7) | (1u << 10) | ((256u / 8u) << 17) | ((128u / 16u) << 24);
static constexpr uint32_t IDESC_BF16_M256_N256 =
    (1u << 4) | (1u << 7) | (1u << 10) | ((256u / 8u) << 17) | ((256u / 16u) << 24);

static constexpr int OFF_TMEMPTR = 0;
static constexpr int OFF_FULL    = 16;    // full[2]
static constexpr int OFF_MMA     = 64;    // mma[2]
static constexpr int OFF_MASK    = 1024;  // 256 floats
static constexpr int SMEM_STAGE0 = 2048;

// --- T2-K64 cg2 engine: 2 M-tiles share B per K=64 stage (SW128), NBUF=2 ---
static constexpr int NBUF = 2;
static constexpr int T2_A0HI = 0,     T2_A0LO = 16384;
static constexpr int T2_A1HI = 32768, T2_A1LO = 49152;
static constexpr int T2_BHI  = 65536, T2_BLO  = 81920;
static constexpr int T2_BYTES = 98304;                  // 6 x 16KB per CTA
static constexpr int T2_SMEM  = SMEM_STAGE0 + NBUF * T2_BYTES;   // 198656

// --- fallback: cp.async cg1, 2 stages of K=64 (SW128) ---
static constexpr int OFF_AHI = 0, OFF_ALO = 16384, OFF_BHI = 32768, OFF_BLO = 65536;
static constexpr int STAGE_BYTES = 98304;
static constexpr int FB_SMEM     = SMEM_STAGE0 + 2 * STAGE_BYTES;   // 198656

// ---------------------------------------------------------------------------
// T2-K64 cg2 GEMM: cluster(2,1) pair computes TWO 256x256 tiles (m0, m0+256)
// sharing the B tile per K=64 stage (24 MMAs/stage = 3072 tensor-cycles,
// amortizing the fixed per-stage handshake). TMEM: tile0 = cols 0-255,
// tile1 = cols 256-511.
//   grid: x = M/256 (pair idx = x>>1), y = N/256, z = batch
// ---------------------------------------------------------------------------
template<bool MASK>
__global__ __launch_bounds__(128, 1) __cluster_dims__(2, 1, 1)
void mma_gemm_t2(const __grid_constant__ CUtensorMap mapAhi,
                 const __grid_constant__ CUtensorMap mapAlo,
                 const __grid_constant__ CUtensorMap mapBhi,
                 const __grid_constant__ CUtensorMap mapBlo,
                 const float* __restrict__ Eg, float* __restrict__ Cg,
                 int M, int N, int K)
{
#if TC_OK
    extern __shared__ char smem[];
    const uint32_t sb = smem_u32(smem);
    const int tid = threadIdx.x;
    const int wid = tid >> 5, lid = tid & 31;
    const int b   = blockIdx.z;
    const int mB  = (blockIdx.x >> 1) * 512;   // PAIR tile base
    const int nB  = blockIdx.y * 256;
    uint32_t rank;
    asm("mov.u32 %0, %%cluster_ctarank;" : "=r"(rank));
    const bool leader = (rank == 0);

    const int S = K / 64;

    if (wid == 0) TCG_ALLOC_CG2(sb + OFF_TMEMPTR, 512);
    if (tid == 0) {
        #pragma unroll
        for (int i = 0; i < NBUF; i++) {
            mbar_init(sb + OFF_FULL + 8 * i, 1);
            mbar_init(sb + OFF_MMA  + 8 * i, 1);
        }
    }
    __syncthreads();
    uint32_t tmem;
    asm volatile("ld.shared.b32 %0, [%1];" : "=r"(tmem) : "r"(sb + OFF_TMEMPTR));

    CLUSTER_SYNC_ALL();   // barriers visible before any cg2 TMA / commit

    const int aRow0 = b * M + mB + (int)rank * 128;        // tile0: own 128 rows
    const int aRow1 = aRow0 + 256;                         // tile1
    const int bRow  = b * N + nB + (int)rank * 128;        // B: own 128 n-rows

    if (wid == 1 && lid == 0) {
        // ---- producer (both CTAs): 6 local cg2 loads per stage ----
        uint32_t phm = 0u;
        for (int s = 0; s < S; s++) {
            const int buf = s % NBUF;
            if (s >= NBUF) {
                mbar_wait(sb + OFF_MMA + 8 * buf, (phm >> buf) & 1u);
                phm ^= 1u << buf;
            }
            const uint32_t st   = sb + SMEM_STAGE0 + buf * T2_BYTES;
            const uint32_t fbar = sb + OFF_FULL + 8 * buf;
            if (leader) mbar_expect(fbar, 2 * T2_BYTES);   // both CTAs' bytes
            const int k0 = s * 64;
            tma2d_cg2(st + T2_A0HI, &mapAhi, k0, aRow0, fbar);
            tma2d_cg2(st + T2_A0LO, &mapAlo, k0, aRow0, fbar);
            tma2d_cg2(st + T2_A1HI, &mapAhi, k0, aRow1, fbar);
            tma2d_cg2(st + T2_A1LO, &mapAlo, k0, aRow1, fbar);
            tma2d_cg2(st + T2_BHI,  &mapBhi, k0, bRow,  fbar);
            tma2d_cg2(st + T2_BLO,  &mapBlo, k0, bRow,  fbar);
        }
        for (int t = (S >= NBUF ? S - NBUF : 0); t < S; t++) {
            const int buf = t % NBUF;
            mbar_wait(sb + OFF_MMA + 8 * buf, (phm >> buf) & 1u);
            phm ^= 1u << buf;
        }
    } else if (wid == 0 && leader) {
        // ---- consumer: leader issues the pair MMAs for BOTH tiles ----
        uint32_t phf = 0u;
        for (int s = 0; s < S; s++) {
            const int buf = s % NBUF;
            mbar_wait(sb + OFF_FULL + 8 * buf, (phf >> buf) & 1u);
            phf ^= 1u << buf;
            if (elect_one()) {
                const uint32_t st = sb + SMEM_STAGE0 + buf * T2_BYTES;
                uint64_t da0h = make_desc128(st + T2_A0HI);
                uint64_t da0l = make_desc128(st + T2_A0LO);
                uint64_t da1h = make_desc128(st + T2_A1HI);
                uint64_t da1l = make_desc128(st + T2_A1LO);
                uint64_t dbh  = make_desc128(st + T2_BHI);
                uint64_t dbl  = make_desc128(st + T2_BLO);
                #pragma unroll
                for (int k = 0; k < 4; k++) {   // four K=16 chunks per 128B row
                    bool en0 = !(s == 0 && k == 0);
                    // tile0 -> TMEM cols 0..255
                    mma_ss_cg2(tmem,       da0h + 2*k, dbh + 2*k, IDESC_BF16_M256_N256, en0);
                    mma_ss_cg2(tmem,       da0h + 2*k, dbl + 2*k, IDESC_BF16_M256_N256, true);
                    mma_ss_cg2(tmem,       da0l + 2*k, dbh + 2*k, IDESC_BF16_M256_N256, true);
                    // tile1 -> TMEM cols 256..511
                    mma_ss_cg2(tmem + 256, da1h + 2*k, dbh + 2*k, IDESC_BF16_M256_N256, en0);
                    mma_ss_cg2(tmem + 256, da1h + 2*k, dbl + 2*k, IDESC_BF16_M256_N256, true);
                    mma_ss_cg2(tmem + 256, da1l + 2*k, dbh + 2*k, IDESC_BF16_M256_N256, true);
                }
                TCG_COMMIT_CG2_MC(sb + OFF_MMA + 8 * buf, 0x3);
            }
        }
    }

    __syncthreads();      // producers verified all commits landed
    TCG_FENCE_AFTER();

    // pad mask (scores only)
    float* mS = (float*)(smem + OFF_MASK);
    if (MASK) {
        for (int i = tid; i < 256; i += 128)
            mS[i] = (Eg[((size_t)b * N + nB + i) * HDIM] == 0.0f) ? 1.0f : 0.0f;
        __syncthreads();
    }

    // epilogue: two tiles; this CTA's TMEM holds its own 128 rows x 256 cols each
    #pragma unroll
    for (int t = 0; t < 2; t++) {
        const int row = mB + t * 256 + (int)rank * 128 + wid * 32 + lid;
        float* crow = Cg + ((size_t)b * M + row) * N + nB;
        for (int cc = 0; cc < 8; cc++) {
            uint32_t r[32];
            TCG_LD_X32(r, tmem + t * 256 + cc * 32);
            TCG_WAIT_LD();
            #pragma unroll
            for (int j = 0; j < 32; j += 4) {
                float4 v;
                v.x = __uint_as_float(r[j + 0]);
                v.y = __uint_as_float(r[j + 1]);
                v.z = __uint_as_float(r[j + 2]);
                v.w = __uint_as_float(r[j + 3]);
                if (MASK) {
                    if (mS[cc * 32 + j + 0] != 0.0f) v.x = -CUDART_INF_F;
                    if (mS[cc * 32 + j + 1] != 0.0f) v.y = -CUDART_INF_F;
                    if (mS[cc * 32 + j + 2] != 0.0f) v.z = -CUDART_INF_F;
                    if (mS[cc * 32 + j + 3] != 0.0f) v.w = -CUDART_INF_F;
                }
                *reinterpret_cast<float4*>(crow + cc * 32 + j) = v;
            }
        }
    }

    __syncthreads();
    if (wid == 0) {
        TCG_RELINQ_CG2();
        TCG_DEALLOC_CG2(tmem, 512);
    }
    CLUSTER_SYNC_ALL();   // no CTA exits while the pair MMA may read its smem
#endif // TC_OK
}

// ---------------------------------------------------------------------------
// FALLBACK: cp.async cg1 GEMM (used only if tensormap encode is unavailable)
// ---------------------------------------------------------------------------
__device__ __forceinline__ void load_tile(uint32_t sdst, const bf16* g,
                                          int rows, int ldk, int tid)
{
    for (int idx = tid; idx < rows * 8; idx += 128) {
        int r = idx >> 3, seg = idx & 7;
        uint32_t bo = (uint32_t)(r * 128 + seg * 16);
        cpasync16(sdst + SWZ128(bo), g + (size_t)r * ldk + seg * 8);
    }
}

template<bool MASK>
__global__ __launch_bounds__(128)
void mma_gemm_fb(const bf16* __restrict__ Ahi, const bf16* __restrict__ Alo,
                 const bf16* __restrict__ Bhi, const bf16* __restrict__ Blo,
                 const float* __restrict__ Eg, float* __restrict__ Cg,
                 int M, int N, int K)
{
#if TC_OK
    extern __shared__ char smem[];
    const uint32_t sb  = smem_u32(smem);
    const int tid = threadIdx.x;
    const int wid = tid >> 5, lid = tid & 31;
    const int b   = blockIdx.z;
    const int mB  = blockIdx.y * 128;
    const int nB  = blockIdx.x * 256;

    const bf16* aH = Ahi + ((size_t)b * M + mB) * K;
    const bf16* aL = Alo + ((size_t)b * M + mB) * K;
    const bf16* bH = Bhi + ((size_t)b * N + nB) * K;
    const bf16* bL = Blo + ((size_t)b * N + nB) * K;

    if (wid == 0) TCG_ALLOC(sb + OFF_TMEMPTR, 256);
    if (tid == 0) {
        mbar_init(sb + OFF_MMA, 1);
        mbar_init(sb + OFF_MMA + 8, 1);
    }
    __syncthreads();
    uint32_t tmem;
    asm volatile("ld.shared.b32 %0, [%1];" : "=r"(tmem) : "r"(sb + OFF_TMEMPTR));

    const int S = K / 64;
    {
        uint32_t st = sb + SMEM_STAGE0;
        load_tile(st + OFF_AHI, aH, 128, K, tid);
        load_tile(st + OFF_ALO, aL, 128, K, tid);
        load_tile(st + OFF_BHI, bH, 256, K, tid);
        load_tile(st + OFF_BLO, bL, 256, K, tid);
        asm volatile("cp.async.commit_group;" ::: "memory");
    }
    uint32_t ph[2] = {0u, 0u};
    for (int s = 0; s < S; s++) {
        const int buf  = s & 1;
        const int nbuf = buf ^ 1;
        if (s + 1 < S) {
            if (s >= 1) {
                mbar_wait(sb + OFF_MMA + 8 * nbuf, ph[nbuf]);
                ph[nbuf] ^= 1;
            }
            const int k0 = (s + 1) * 64;
            uint32_t st = sb + SMEM_STAGE0 + nbuf * STAGE_BYTES;
            load_tile(st + OFF_AHI, aH + k0, 128, K, tid);
            load_tile(st + OFF_ALO, aL + k0, 128, K, tid);
            load_tile(st + OFF_BHI, bH + k0, 256, K, tid);
            load_tile(st + OFF_BLO, bL + k0, 256, K, tid);
            asm volatile("cp.async.commit_group;" ::: "memory");
            asm volatile("cp.async.wait_group 1;" ::: "memory");
        } else {
            asm volatile("cp.async.wait_group 0;" ::: "memory");
        }
        __syncthreads();
        if (wid == 0) {
            asm volatile("fence.proxy.async.shared::cta;" ::: "memory");
            if (elect_one()) {
                uint32_t st = sb + SMEM_STAGE0 + buf * STAGE_BYTES;
                uint64_t dah = make_desc128(st + OFF_AHI);
                uint64_t dal = make_desc128(st + OFF_ALO);
                uint64_t dbh = make_desc128(st + OFF_BHI);
                uint64_t dbl = make_desc128(st + OFF_BLO);
                #pragma unroll
                for (int k = 0; k < 4; k++) {
                    bool en0 = !(s == 0 && k == 0);
                    mma_ss(tmem, dah + 2 * k, dbh + 2 * k, IDESC_BF16_M128_N256, en0);
                    mma_ss(tmem, dah + 2 * k, dbl + 2 * k, IDESC_BF16_M128_N256, true);
                    mma_ss(tmem, dal + 2 * k, dbh + 2 * k, IDESC_BF16_M128_N256, true);
                }
                TCG_COMMIT(sb + OFF_MMA + 8 * buf);
            }
        }
    }
    const int lb = (S - 1) & 1;
    mbar_wait(sb + OFF_MMA + 8 * lb, ph[lb]);
    TCG_FENCE_AFTER();

    float* mS = (float*)(smem + OFF_MASK);
    if (MASK) {
        for (int i = tid; i < 256; i += 128)
            mS[i] = (Eg[((size_t)b * N + nB + i) * HDIM] == 0.0f) ? 1.0f : 0.0f;
    }
    __syncthreads();

    const int row = mB + wid * 32 + lid;
    float* crow = Cg + ((size_t)b * M + row) * N + nB;
    for (int cc = 0; cc < 8; cc++) {
        uint32_t r[32];
        TCG_LD_X32(r, tmem + cc * 32);
        TCG_WAIT_LD();
        #pragma unroll
        for (int j = 0; j < 32; j += 4) {
            float4 v;
            v.x = __uint_as_float(r[j + 0]);
            v.y = __uint_as_float(r[j + 1]);
            v.z = __uint_as_float(r[j + 2]);
            v.w = __uint_as_float(r[j + 3]);
            if (MASK) {
                if (mS[cc * 32 + j + 0] != 0.0f) v.x = -CUDART_INF_F;
                if (mS[cc * 32 + j + 1] != 0.0f) v.y = -CUDART_INF_F;
                if (mS[cc * 32 + j + 2] != 0.0f) v.z = -CUDART_INF_F;
                if (mS[cc * 32 + j + 3] != 0.0f) v.w = -CUDART_INF_F;
            }
            *reinterpret_cast<float4*>(crow + cc * 32 + j) = v;
        }
    }
    __syncthreads();
    if (wid == 0) {
        TCG_RELINQ();
        TCG_DEALLOC(tmem, 256);
    }
#endif // TC_OK
}

// ---------------------------------------------------------------------------
// Row softmax (2048), in place, also emits P hi/lo bf16.
// ---------------------------------------------------------------------------
__inline__ __device__ float warpMax(float v) {
    #pragma unroll
    for (int o = 16; o > 0; o >>= 1) v = fmaxf(v, __shfl_xor_sync(0xffffffffu, v, o));
    return v;
}
__inline__ __device__ float warpSum(float v) {
    #pragma unroll
    for (int o = 16; o > 0; o >>= 1) v += __shfl_xor_sync(0xffffffffu, v, o);
    return v;
}

__global__ __launch_bounds__(256)
void softmax_split_kernel(float* __restrict__ attn,
                          bf16* __restrict__ Phi, bf16* __restrict__ Plo)
{
    const size_t row = blockIdx.x;
    float* p = attn + row * (size_t)ENC;
    const int tid = threadIdx.x;

    float4 v0 = reinterpret_cast<float4*>(p)[tid];
    float4 v1 = reinterpret_cast<float4*>(p)[tid + 256];

    __shared__ float smax[8];
    __shared__ float ssum[8];

    float m = fmaxf(fmaxf(fmaxf(v0.x, v0.y), fmaxf(v0.z, v0.w)),
                    fmaxf(fmaxf(v1.x, v1.y), fmaxf(v1.z, v1.w)));
    float wm = warpMax(m);
    if ((tid & 31) == 0) smax[tid >> 5] = wm;
    __syncthreads();
    if (tid < 32) {
        float t = (tid < 8) ? smax[tid] : -CUDART_INF_F;
        t = warpMax(t);
        if (tid == 0) smax[0] = t;
    }
    __syncthreads();
    const float bm = smax[0];

    v0.x = __expf(v0.x - bm); v0.y = __expf(v0.y - bm);
    v0.z = __expf(v0.z - bm); v0.w = __expf(v0.w - bm);
    v1.x = __expf(v1.x - bm); v1.y = __expf(v1.y - bm);
    v1.z = __expf(v1.z - bm); v1.w = __expf(v1.w - bm);

    float s = (v0.x + v0.y + v0.z + v0.w) + (v1.x + v1.y + v1.z + v1.w);
    float ws = warpSum(s);
    if ((tid & 31) == 0) ssum[tid >> 5] = ws;
    __syncthreads();
    if (tid < 32) {
        float t = (tid < 8) ? ssum[tid] : 0.0f;
        t = warpSum(t);
        if (tid == 0) ssum[0] = t;
    }
    __syncthreads();
    const float inv = 1.0f / ssum[0];

    v0.x *= inv; v0.y *= inv; v0.z *= inv; v0.w *= inv;
    v1.x *= inv; v1.y *= inv; v1.z *= inv; v1.w *= inv;

    reinterpret_cast<float4*>(p)[tid]       = v0;
    reinterpret_cast<float4*>(p)[tid + 256] = v1;

    uint2 h0, l0, h1, l1;
    pack4(v0, h0, l0);
    pack4(v1, h1, l1);
    uint2* ph = reinterpret_cast<uint2*>(Phi + row * (size_t)ENC);
    uint2* pl = reinterpret_cast<uint2*>(Plo + row * (size_t)ENC);
    ph[tid]       = h0;  ph[tid + 256] = h1;
    pl[tid]       = l0;  pl[tid + 256] = l1;
}

// ---------------------------------------------------------------------------
// Host
// ---------------------------------------------------------------------------
typedef CUresult (*EncodeFn)(
    CUtensorMap*, CUtensorMapDataType, cuuint32_t, void*,
    const cuuint64_t*, const cuuint64_t*, const cuuint32_t*, const cuuint32_t*,
    CUtensorMapInterleave, CUtensorMapSwizzle, CUtensorMapL2promotion,
    CUtensorMapFloatOOBfill);

static bool encode_sw128(EncodeFn fn, CUtensorMap* m, void* base,
                         uint64_t kdim, uint64_t rows)
{
    cuuint64_t dims[2]    = {kdim, rows};
    cuuint64_t strides[1] = {kdim * 2};
    cuuint32_t box[2]     = {64u, 128u};          // 64 bf16 = 128B (SW128)
    cuuint32_t estr[2]    = {1u, 1u};
    CUresult r = fn(m, CU_TENSOR_MAP_DATA_TYPE_BFLOAT16, 2, base,
                    dims, strides, box, estr,
                    CU_TENSOR_MAP_INTERLEAVE_NONE, CU_TENSOR_MAP_SWIZZLE_128B,
                    CU_TENSOR_MAP_L2_PROMOTION_L2_128B,
                    CU_TENSOR_MAP_FLOAT_OOB_FILL_NONE);
    return r == CUDA_SUCCESS;
}

extern "C" void kernel_launch(void* const* d_in, const int* in_sizes, int n_in,
                              void* d_out, int out_size)
{
    const float* D = (const float*)d_in[0];
    const float* E = (const float*)d_in[1];

    float* ctx  = (float*)d_out;                        // [16,2048,1024]
    float* attn = ctx + (size_t)BATCH * DEC * HDIM;     // [16,2048,2048]

    void *pDhi, *pDlo, *pEhi, *pElo, *pEThi, *pETlo, *pPhi, *pPlo;
    cudaGetSymbolAddress(&pDhi,  g_Dhi);
    cudaGetSymbolAddress(&pDlo,  g_Dlo);
    cudaGetSymbolAddress(&pEhi,  g_Ehi);
    cudaGetSymbolAddress(&pElo,  g_Elo);
    cudaGetSymbolAddress(&pEThi, g_EThi);
    cudaGetSymbolAddress(&pETlo, g_ETlo);
    cudaGetSymbolAddress(&pPhi,  g_Phi);
    cudaGetSymbolAddress(&pPlo,  g_Plo);

    cudaFuncSetAttribute(mma_gemm_t2<true>,
                         cudaFuncAttributeMaxDynamicSharedMemorySize, T2_SMEM);
    cudaFuncSetAttribute(mma_gemm_t2<false>,
                         cudaFuncAttributeMaxDynamicSharedMemorySize, T2_SMEM);
    cudaFuncSetAttribute(mma_gemm_fb<true>,
                         cudaFuncAttributeMaxDynamicSharedMemorySize, FB_SMEM);
    cudaFuncSetAttribute(mma_gemm_fb<false>,
                         cudaFuncAttributeMaxDynamicSharedMemorySize, FB_SMEM);

    EncodeFn enc = nullptr;
    {
        void* fp = nullptr;
        cudaDriverEntryPointQueryResult qr = cudaDriverEntryPointSymbolNotFound;
        if (cudaGetDriverEntryPoint("cuTensorMapEncodeTiled", &fp,
                                    cudaEnableDefault, &qr) == cudaSuccess &&
            qr == cudaDriverEntryPointSuccess)
            enc = (EncodeFn)fp;
    }

    CUtensorMap mDhi, mDlo, mEhi, mElo, mPhi, mPlo, mEThi, mETlo;
    bool tma_ok = (enc != nullptr);
    if (tma_ok) {
        tma_ok =
            encode_sw128(enc, &mDhi,  pDhi,  HDIM, (uint64_t)BATCH * DEC)  &&
            encode_sw128(enc, &mDlo,  pDlo,  HDIM, (uint64_t)BATCH * DEC)  &&
            encode_sw128(enc, &mEhi,  pEhi,  HDIM, (uint64_t)BATCH * ENC)  &&
            encode_sw128(enc, &mElo,  pElo,  HDIM, (uint64_t)BATCH * ENC)  &&
            encode_sw128(enc, &mPhi,  pPhi,  ENC,  (uint64_t)BATCH * DEC)  &&
            encode_sw128(enc, &mPlo,  pPlo,  ENC,  (uint64_t)BATCH * DEC)  &&
            encode_sw128(enc, &mEThi, pEThi, ENC,  (uint64_t)BATCH * HDIM) &&
            encode_sw128(enc, &mETlo, pETlo, ENC,  (uint64_t)BATCH * HDIM);
    }

    const int n4 = BATCH * DEC * HDIM / 4;
    split_kernel<<<n4 / 256, 256>>>((const float4*)D, (uint2*)pDhi, (uint2*)pDlo, n4);

    // fused: E read once -> Ehi/Elo (row-major) + EThi/ETlo (transposed)
    fused_split_transpose_kernel<<<dim3(ENC / 32, HDIM / 32, BATCH), dim3(32, 8)>>>(
        E, (bf16*)pEhi, (bf16*)pElo, (bf16*)pEThi, (bf16*)pETlo);

    if (tma_ok) {
        // scores: M=DEC, N=ENC, K=HDIM; grid x = M/256 (CTA pairs), y = N/256
        mma_gemm_t2<true><<<dim3(DEC / 256, ENC / 256, BATCH), 128, T2_SMEM>>>(
            mDhi, mDlo, mEhi, mElo, E, attn, DEC, ENC, HDIM);
    } else {
        mma_gemm_fb<true><<<dim3(ENC / 256, DEC / 128, BATCH), 128, FB_SMEM>>>(
            (const bf16*)pDhi, (const bf16*)pDlo,
            (const bf16*)pEhi, (const bf16*)pElo, E, attn, DEC, ENC, HDIM);
    }

    softmax_split_kernel<<<BATCH * DEC, 256>>>(attn, (bf16*)pPhi, (bf16*)pPlo);

    if (tma_ok) {
        // context: M=DEC, N=HDIM, K=ENC; grid x = M/256, y = N/256
        mma_gemm_t2<false><<<dim3(DEC / 256, HDIM / 256, BATCH), 128, T2_SMEM>>>(
            mPhi, mPlo, mEThi, mETlo, nullptr, ctx, DEC, HDIM, ENC);
    } else {
        mma_gemm_fb<false><<<dim3(HDIM / 256, DEC / 128, BATCH), 128, FB_SMEM>>>(
            (const bf16*)pPhi, (const bf16*)pPlo,
            (const bf16*)pEThi, (const bf16*)pETlo, nullptr, ctx, DEC, HDIM, ENC);
    }
}